// round 1
// baseline (speedup 1.0000x reference)
#include <cuda_runtime.h>
#include <math.h>
#include <stddef.h>

#define BB 2
#define SS 2048
#define HH 1024
#define NHD 16
#define HD 64
#define MM (BB*SS)   /* 4096 */

// Scratch for projected Q/K/V in head-major layout [B, NH, S, HD]
__device__ float g_Q[BB*NHD*SS*HD];
__device__ float g_K[BB*NHD*SS*HD];
__device__ float g_V[BB*NHD*SS*HD];

// ---------------------------------------------------------------------------
// Projection GEMM: out[b,h,s,d] = (sum_k X[m,k]*W[n,k] + bias[n]) * scale
// X: [M=4096, K=1024], W: [N=1024, K=1024] (row-major, K contiguous)
// BM=128, BN=64, BK=16, 256 threads, 8x4 register tiles.
// ---------------------------------------------------------------------------
#define PBM 128
#define PBN 64
#define PBK 16

__global__ __launch_bounds__(256) void proj_kernel(
    const float* __restrict__ X, const float* __restrict__ W,
    const float* __restrict__ bias, float* __restrict__ out, float scale)
{
    __shared__ float As[PBK][PBM];
    __shared__ float Bs[PBK][PBN];

    const int t  = threadIdx.x;
    const int m0 = blockIdx.y * PBM;
    const int n0 = blockIdx.x * PBN;

    const int kv = t >> 6;       // 0..3 -> k-vector within tile
    const int lr = t & 63;       // row within loader group
    const int tm0 = (t >> 4) << 3;  // 0,8,...,120
    const int tn0 = (t & 15) << 2;  // 0,4,...,60

    float acc[8][4];
#pragma unroll
    for (int i = 0; i < 8; i++)
#pragma unroll
        for (int j = 0; j < 4; j++) acc[i][j] = 0.f;

    for (int k0 = 0; k0 < HH; k0 += PBK) {
        // stage global loads into registers
        float4 a0 = *(const float4*)&X[(size_t)(m0 + lr)      * HH + k0 + kv * 4];
        float4 a1 = *(const float4*)&X[(size_t)(m0 + lr + 64) * HH + k0 + kv * 4];
        float4 b0 = *(const float4*)&W[(size_t)(n0 + lr)      * HH + k0 + kv * 4];

        __syncthreads();  // previous tile fully consumed
        As[kv*4+0][lr] = a0.x; As[kv*4+1][lr] = a0.y;
        As[kv*4+2][lr] = a0.z; As[kv*4+3][lr] = a0.w;
        As[kv*4+0][lr+64] = a1.x; As[kv*4+1][lr+64] = a1.y;
        As[kv*4+2][lr+64] = a1.z; As[kv*4+3][lr+64] = a1.w;
        Bs[kv*4+0][lr] = b0.x; Bs[kv*4+1][lr] = b0.y;
        Bs[kv*4+2][lr] = b0.z; Bs[kv*4+3][lr] = b0.w;
        __syncthreads();

#pragma unroll
        for (int k = 0; k < PBK; k++) {
            float4 aA = *(const float4*)&As[k][tm0];
            float4 aB = *(const float4*)&As[k][tm0 + 4];
            float4 bb = *(const float4*)&Bs[k][tn0];
            float a[8] = {aA.x, aA.y, aA.z, aA.w, aB.x, aB.y, aB.z, aB.w};
            float b[4] = {bb.x, bb.y, bb.z, bb.w};
#pragma unroll
            for (int ii = 0; ii < 8; ii++)
#pragma unroll
                for (int jj = 0; jj < 4; jj++) acc[ii][jj] += a[ii] * b[jj];
        }
    }

    // epilogue: bias + scale, write head-major [b, head, s, d]
    float4 bvec = *(const float4*)&bias[n0 + tn0];
    const int head = n0 >> 6;   // BN==HD: one head per block column
#pragma unroll
    for (int ii = 0; ii < 8; ii++) {
        int m = m0 + tm0 + ii;
        int b = m >> 11;        // m / 2048
        int s = m & 2047;
        float4 r;
        r.x = (acc[ii][0] + bvec.x) * scale;
        r.y = (acc[ii][1] + bvec.y) * scale;
        r.z = (acc[ii][2] + bvec.z) * scale;
        r.w = (acc[ii][3] + bvec.w) * scale;
        *(float4*)&out[((size_t)(b * NHD + head) * SS + s) * HD + tn0] = r;
    }
}

// ---------------------------------------------------------------------------
// Flash attention: one block per (b, h, 64-query tile). 128 threads.
// Online softmax over 32 K/V tiles of 64 rows. fp32 throughout.
// ---------------------------------------------------------------------------
#define ATTN_SMEM_FLOATS (64*64 + 64*68 + 64*68 + 128 + 64 + 64 + 64 + 64)
#define ATTN_SMEM_BYTES  (ATTN_SMEM_FLOATS * 4)

__global__ __launch_bounds__(128, 4) void attn_kernel(
    const float* __restrict__ Q, const float* __restrict__ K,
    const float* __restrict__ V, const float* __restrict__ mask,
    float* __restrict__ out)
{
    extern __shared__ float sm[];
    float* Qt   = sm;                 // [64 d][64 i]   Qt[d*64+i]
    float* KV   = Qt + 64*64;         // Kt[d*64+j] OR Vs[j*68+c]  (64*68 floats)
    float* Sx   = KV + 64*68;         // [64 j][68 pad] Sx[j*68+i]
    float* tmp  = Sx + 64*68;         // [128]
    float* mrow = tmp + 128;          // [64]
    float* lrow = mrow + 64;          // [64]
    float* frow = lrow + 64;          // [64]
    float* msk  = frow + 64;          // [64]

    const int t  = threadIdx.x;
    const int q0 = blockIdx.x * 64;
    const int h  = blockIdx.y;
    const int bz = blockIdx.z;

    const float* qg     = Q + ((size_t)(bz * NHD + h) * SS + q0) * HD;
    const float* kgbase = K + (size_t)(bz * NHD + h) * SS * HD;
    const float* vgbase = V + (size_t)(bz * NHD + h) * SS * HD;
    const float* mbase  = mask + (size_t)bz * SS;

    // load Q tile transposed (d-major)
    {
        int i = t & 63, dv = t >> 6;
#pragma unroll
        for (int u = 0; u < 8; u++) {
            int d = dv * 32 + u * 4;
            float4 v4 = *(const float4*)&qg[i * HD + d];
            Qt[(d+0)*64 + i] = v4.x;
            Qt[(d+1)*64 + i] = v4.y;
            Qt[(d+2)*64 + i] = v4.z;
            Qt[(d+3)*64 + i] = v4.w;
        }
    }
    if (t < 64) { mrow[t] = -1e30f; lrow[t] = 0.f; }

    const int i0  = (t >> 4) << 3;  // 0,8,...,56 (query rows owned)
    const int c0  = (t & 15) << 2;  // 0,4,...,60 (S columns / O dims owned)

    float o[8][4];
#pragma unroll
    for (int ii = 0; ii < 8; ii++)
#pragma unroll
        for (int cc = 0; cc < 4; cc++) o[ii][cc] = 0.f;

    for (int kt = 0; kt < SS / 64; kt++) {
        const float* kg = kgbase + (size_t)kt * 64 * HD;
        const float* vg = vgbase + (size_t)kt * 64 * HD;

        __syncthreads();  // prev O-update (reads Vs) done; Qt ready on iter 0
        // load K tile transposed (d-major) + mask slice
        {
            int j = t & 63, dv = t >> 6;
#pragma unroll
            for (int u = 0; u < 8; u++) {
                int d = dv * 32 + u * 4;
                float4 v4 = *(const float4*)&kg[j * HD + d];
                KV[(d+0)*64 + j] = v4.x;
                KV[(d+1)*64 + j] = v4.y;
                KV[(d+2)*64 + j] = v4.z;
                KV[(d+3)*64 + j] = v4.w;
            }
            if (t < 64) msk[t] = mbase[kt * 64 + t];
        }
        __syncthreads();

        // S = Q * K^T  (scale already folded into Q)
        float sacc[8][4];
#pragma unroll
        for (int ii = 0; ii < 8; ii++)
#pragma unroll
            for (int jj = 0; jj < 4; jj++) sacc[ii][jj] = 0.f;

#pragma unroll 8
        for (int d = 0; d < 64; d++) {
            float4 qa = *(const float4*)&Qt[d*64 + i0];
            float4 qb = *(const float4*)&Qt[d*64 + i0 + 4];
            float4 kb = *(const float4*)&KV[d*64 + c0];
            float a[8] = {qa.x, qa.y, qa.z, qa.w, qb.x, qb.y, qb.z, qb.w};
            float b[4] = {kb.x, kb.y, kb.z, kb.w};
#pragma unroll
            for (int ii = 0; ii < 8; ii++)
#pragma unroll
                for (int jj = 0; jj < 4; jj++) sacc[ii][jj] += a[ii] * b[jj];
        }
        // write S (+additive mask)
        {
            float mk[4] = {msk[c0], msk[c0+1], msk[c0+2], msk[c0+3]};
#pragma unroll
            for (int jj = 0; jj < 4; jj++)
#pragma unroll
                for (int ii = 0; ii < 8; ii++)
                    Sx[(c0+jj)*68 + i0 + ii] = sacc[ii][jj] + mk[jj];
        }
        __syncthreads();  // Sx ready, Kt reads done

        // load V tile (natural layout) into the KV buffer
        {
            int j = t >> 1, ch = (t & 1) * 32;
#pragma unroll
            for (int u = 0; u < 8; u++) {
                float4 v4 = *(const float4*)&vg[j * HD + ch + u * 4];
                *(float4*)&KV[j*68 + ch + u*4] = v4;
            }
        }
        // pass A: per-column (query row) tile max
        {
            int i = t & 63, jb = (t >> 6) * 32;
            float tm = -1e30f;
#pragma unroll 8
            for (int jj = 0; jj < 32; jj++)
                tm = fmaxf(tm, Sx[(jb+jj)*68 + i]);
            tmp[t] = tm;
        }
        __syncthreads();
        if (t < 64) {
            float mt = fmaxf(tmp[t], tmp[t+64]);
            float mo = mrow[t];
            float mn = fmaxf(mo, mt);
            frow[t] = __expf(mo - mn);
            mrow[t] = mn;
        }
        __syncthreads();
        // pass B: exponentiate in place + partial sums
        {
            int i = t & 63, jb = (t >> 6) * 32;
            float mi = mrow[i];
            float es = 0.f;
#pragma unroll 8
            for (int jj = 0; jj < 32; jj++) {
                float e = __expf(Sx[(jb+jj)*68 + i] - mi);
                Sx[(jb+jj)*68 + i] = e;
                es += e;
            }
            tmp[t] = es;
        }
        __syncthreads();
        if (t < 64) lrow[t] = lrow[t] * frow[t] + tmp[t] + tmp[t+64];

        // O update: rescale by frow, accumulate P*V
        {
            float fr[8];
#pragma unroll
            for (int ii = 0; ii < 8; ii++) fr[ii] = frow[i0 + ii];
#pragma unroll
            for (int ii = 0; ii < 8; ii++)
#pragma unroll
                for (int cc = 0; cc < 4; cc++) o[ii][cc] *= fr[ii];
        }
#pragma unroll 4
        for (int j = 0; j < 64; j++) {
            float4 p0 = *(const float4*)&Sx[j*68 + i0];
            float4 p1 = *(const float4*)&Sx[j*68 + i0 + 4];
            float4 vv = *(const float4*)&KV[j*68 + c0];
            float p[8] = {p0.x, p0.y, p0.z, p0.w, p1.x, p1.y, p1.z, p1.w};
            float v[4] = {vv.x, vv.y, vv.z, vv.w};
#pragma unroll
            for (int ii = 0; ii < 8; ii++)
#pragma unroll
                for (int cc = 0; cc < 4; cc++) o[ii][cc] += p[ii] * v[cc];
        }
    }

    __syncthreads();  // lrow of last tile visible
#pragma unroll
    for (int ii = 0; ii < 8; ii++) {
        float inv = 1.f / lrow[i0 + ii];
        int s = q0 + i0 + ii;
        float4 r;
        r.x = o[ii][0] * inv;
        r.y = o[ii][1] * inv;
        r.z = o[ii][2] * inv;
        r.w = o[ii][3] * inv;
        *(float4*)&out[((size_t)(bz * SS + s)) * HH + h * HD + c0] = r;
    }
}

// ---------------------------------------------------------------------------
extern "C" void kernel_launch(void* const* d_in, const int* in_sizes, int n_in,
                              void* d_out, int out_size)
{
    const float* query = (const float*)d_in[0];
    const float* key   = (const float*)d_in[1];
    const float* value = (const float*)d_in[2];
    const float* amask = (const float*)d_in[3];
    const float* Wq    = (const float*)d_in[4];
    const float* bq    = (const float*)d_in[5];
    const float* Wk    = (const float*)d_in[6];
    const float* bk    = (const float*)d_in[7];
    const float* Wv    = (const float*)d_in[8];
    const float* bv    = (const float*)d_in[9];
    float* out = (float*)d_out;

    float *qP, *kP, *vP;
    cudaGetSymbolAddress((void**)&qP, g_Q);
    cudaGetSymbolAddress((void**)&kP, g_K);
    cudaGetSymbolAddress((void**)&vP, g_V);

    // opt-in >48KB dynamic smem (idempotent; executed on the pre-capture call too)
    cudaFuncSetAttribute(attn_kernel,
                         cudaFuncAttributeMaxDynamicSharedMemorySize,
                         ATTN_SMEM_BYTES);

    dim3 pg(HH / PBN, MM / PBM);  // (16, 32)
    proj_kernel<<<pg, 256>>>(query, Wq, bq, qP, 0.125f);  // fold 1/sqrt(64) into Q
    proj_kernel<<<pg, 256>>>(key,   Wk, bk, kP, 1.0f);
    proj_kernel<<<pg, 256>>>(value, Wv, bv, vP, 1.0f);

    dim3 ag(SS / 64, NHD, BB);    // (32, 16, 2)
    attn_kernel<<<ag, 128, ATTN_SMEM_BYTES>>>(qP, kP, vP, amask, out);
}

// round 8
// speedup vs baseline: 2.2906x; 2.2906x over previous
#include <cuda_runtime.h>
#include <cuda_bf16.h>
#include <stdint.h>
#include <stddef.h>

#define BB 2
#define SS 2048
#define HH 1024
#define NHD 16
#define HD 64
#define MM (BB*SS)   /* 4096 */

// Projected tensors, pre-split bf16 (value ~= hi + lo).
// Q, K: [b, h, s, d] row-major.   V: [b, h, d, s] (transposed).
__device__ __align__(16) __nv_bfloat16 g_Qh[BB*NHD*SS*HD];
__device__ __align__(16) __nv_bfloat16 g_Ql[BB*NHD*SS*HD];
__device__ __align__(16) __nv_bfloat16 g_Kh[BB*NHD*SS*HD];
__device__ __align__(16) __nv_bfloat16 g_Kl[BB*NHD*SS*HD];
__device__ __align__(16) __nv_bfloat16 g_Vh[BB*NHD*SS*HD];
__device__ __align__(16) __nv_bfloat16 g_Vl[BB*NHD*SS*HD];

// ---------------------------------------------------------------------------
// helpers
// ---------------------------------------------------------------------------
__device__ __forceinline__ uint32_t smem_u32(const void* p) {
    uint32_t a;
    asm("{ .reg .u64 t; cvta.to.shared.u64 t, %1; cvt.u32.u64 %0, t; }"
        : "=r"(a) : "l"(p));
    return a;
}

// split (x, y) -> packed bf16x2 hi + bf16x2 lo  (x ~= hi.x + lo.x)
__device__ __forceinline__ void split2(float x, float y, uint32_t& h, uint32_t& l) {
    __nv_bfloat162 hh = __floats2bfloat162_rn(x, y);
    float2 hf = __bfloat1622float2(hh);
    __nv_bfloat162 ll = __floats2bfloat162_rn(x - hf.x, y - hf.y);
    h = *reinterpret_cast<uint32_t*>(&hh);
    l = *reinterpret_cast<uint32_t*>(&ll);
}

__device__ __forceinline__ void ldm_x4(uint32_t r[4], uint32_t addr) {
    asm volatile("ldmatrix.sync.aligned.m8n8.x4.shared.b16 {%0,%1,%2,%3}, [%4];"
                 : "=r"(r[0]), "=r"(r[1]), "=r"(r[2]), "=r"(r[3]) : "r"(addr));
}

__device__ __forceinline__ void mma_bf16(float c[4], const uint32_t a[4],
                                         uint32_t b0, uint32_t b1) {
    asm volatile("mma.sync.aligned.m16n8k16.row.col.f32.bf16.bf16.f32 "
                 "{%0,%1,%2,%3}, {%4,%5,%6,%7}, {%8,%9}, {%0,%1,%2,%3};"
                 : "+f"(c[0]), "+f"(c[1]), "+f"(c[2]), "+f"(c[3])
                 : "r"(a[0]), "r"(a[1]), "r"(a[2]), "r"(a[3]), "r"(b0), "r"(b1));
}

#define STS64(addr, r0, r1) \
    asm volatile("st.shared.v2.b32 [%0], {%1,%2};" :: "r"(addr), "r"(r0), "r"(r1) : "memory")

// ===========================================================================
// Projection GEMM via mma.sync, bf16x3 split.
//   C[m,n] = sum_k A[m,k] * B[n,k]   (both row-major, K=1024 contiguous)
// MODE 0 (Q/K): A = X(4096xK), B = W(1024xK). out = (C + bias[n]) * scale,
//               split bf16 hi/lo, stored [b, h, s, d].
// MODE 1 (V):   A = W(1024xK), B = X(4096xK) -> C = (X@W^T)^T. out stored
//               transposed [b, h, d, s] with bias[m-row] (coalesced along s).
// CTA 128x128, BK=32, 8 warps (warp tile 64x32).
// ===========================================================================
#define PJ_BK 32
#define PJ_STRIDE 40                    /* bf16 per smem row: 32 + 8 pad */
#define PJ_ROWB (PJ_STRIDE*2)           /* 80 bytes */
#define PJ_MAT (128*PJ_ROWB)            /* 10240 bytes per matrix */

template <int MODE>
__global__ __launch_bounds__(256, 1) void proj_mma_kernel(
    const float* __restrict__ A, const float* __restrict__ B,
    const float* __restrict__ bias,
    __nv_bfloat16* __restrict__ outH, __nv_bfloat16* __restrict__ outL,
    float scale)
{
    __shared__ __align__(16) uint8_t psm[4 * PJ_MAT];   // AH, AL, BH, BL
    const uint32_t sb = smem_u32(psm);
    const uint32_t AH = sb, AL = sb + PJ_MAT, BH = sb + 2*PJ_MAT, BL = sb + 3*PJ_MAT;

    const int t   = threadIdx.x;
    const int wid = t >> 5;
    const int l   = t & 31;
    const int m0  = blockIdx.y * 128;
    const int n0  = blockIdx.x * 128;
    const int wm0 = (wid & 1) * 64;
    const int wn0 = (wid >> 1) * 32;

    // ldmatrix per-lane geometry
    const int rowin = (l & 7) + ((l >> 3) & 1) * 8;
    const int colb  = ((l >> 4) & 1) * 8;

    float acc[4][4][4];
#pragma unroll
    for (int mt = 0; mt < 4; mt++)
#pragma unroll
        for (int nt = 0; nt < 4; nt++)
#pragma unroll
            for (int i = 0; i < 4; i++) acc[mt][nt][i] = 0.f;

    const int lrow = t >> 1;            // loader row 0..127
    const int lc8a = (t & 1) * 4;       // float4 index base (2 per thread per rep)

    for (int kt = 0; kt < HH / PJ_BK; kt++) {
        const int k0 = kt * PJ_BK;
        __syncthreads();
        // fill: 128 rows x 32 k. Each thread: 4 float4 from A, 4 from B.
#pragma unroll
        for (int rep = 0; rep < 4; rep++) {
            const int idx = rep * 256 + t;          // 0..1023
            const int row = idx >> 3;
            const int c8  = idx & 7;                // 8-byte bf16 chunk (4 k)
            float4 fa = *(const float4*)&A[(size_t)(m0 + row) * HH + k0 + c8 * 4];
            float4 fb = *(const float4*)&B[(size_t)(n0 + row) * HH + k0 + c8 * 4];
            uint32_t h0, h1, l0, l1;
            split2(fa.x, fa.y, h0, l0); split2(fa.z, fa.w, h1, l1);
            STS64(AH + row * PJ_ROWB + c8 * 8, h0, h1);
            STS64(AL + row * PJ_ROWB + c8 * 8, l0, l1);
            split2(fb.x, fb.y, h0, l0); split2(fb.z, fb.w, h1, l1);
            STS64(BH + row * PJ_ROWB + c8 * 8, h0, h1);
            STS64(BL + row * PJ_ROWB + c8 * 8, l0, l1);
        }
        __syncthreads();

#pragma unroll
        for (int ks = 0; ks < 2; ks++) {
            uint32_t ah[4][4], al[4][4];
#pragma unroll
            for (int mt = 0; mt < 4; mt++) {
                const uint32_t off = (uint32_t)((wm0 + mt*16 + rowin) * PJ_ROWB
                                                + (colb + ks*16) * 2);
                ldm_x4(ah[mt], AH + off);
                ldm_x4(al[mt], AL + off);
            }
            uint32_t bh[4][2], bl[4][2];
#pragma unroll
            for (int np = 0; np < 2; np++) {
                uint32_t r[4];
                const uint32_t off = (uint32_t)((wn0 + np*16 + rowin) * PJ_ROWB
                                                + (colb + ks*16) * 2);
                ldm_x4(r, BH + off);
                bh[2*np][0] = r[0]; bh[2*np][1] = r[2];
                bh[2*np+1][0] = r[1]; bh[2*np+1][1] = r[3];
                ldm_x4(r, BL + off);
                bl[2*np][0] = r[0]; bl[2*np][1] = r[2];
                bl[2*np+1][0] = r[1]; bl[2*np+1][1] = r[3];
            }
#pragma unroll
            for (int mt = 0; mt < 4; mt++)
#pragma unroll
                for (int nt = 0; nt < 4; nt++) {
                    mma_bf16(acc[mt][nt], ah[mt], bh[nt][0], bh[nt][1]);
                    mma_bf16(acc[mt][nt], ah[mt], bl[nt][0], bl[nt][1]);
                    mma_bf16(acc[mt][nt], al[mt], bh[nt][0], bh[nt][1]);
                }
        }
    }

    // epilogue
    const int g    = l >> 2;
    const int tcol = (l & 3) * 2;
#pragma unroll
    for (int mt = 0; mt < 4; mt++) {
#pragma unroll
        for (int nt = 0; nt < 4; nt++) {
            const int gm = m0 + wm0 + mt * 16 + g;
            const int gn = n0 + wn0 + nt * 8 + tcol;
            if (MODE == 0) {
                const float b0 = __ldg(&bias[gn]), b1 = __ldg(&bias[gn + 1]);
                const int head = gn >> 6, d = gn & 63;
#pragma unroll
                for (int i = 0; i < 2; i++) {
                    const int m = gm + i * 8;
                    const int bb = m >> 11, s = m & 2047;
                    uint32_t hw, lw;
                    split2((acc[mt][nt][2*i]   + b0) * scale,
                           (acc[mt][nt][2*i+1] + b1) * scale, hw, lw);
                    const size_t off = ((size_t)(bb * NHD + head) * SS + s) * HD + d;
                    *(uint32_t*)&outH[off] = hw;
                    *(uint32_t*)&outL[off] = lw;
                }
            } else {
                // rows = features, cols = (b, s) pairs; transposed store
                const int bb = gn >> 11, s = gn & 2047;
#pragma unroll
                for (int i = 0; i < 2; i++) {
                    const int feat = gm + i * 8;
                    const float br = __ldg(&bias[feat]);
                    const int head = feat >> 6, d = feat & 63;
                    uint32_t hw, lw;
                    split2((acc[mt][nt][2*i]   + br) * scale,
                           (acc[mt][nt][2*i+1] + br) * scale, hw, lw);
                    const size_t off = ((size_t)(bb * NHD + head) * HD + d) * SS + s;
                    *(uint32_t*)&outH[off] = hw;
                    *(uint32_t*)&outL[off] = lw;
                }
            }
        }
    }
}

// ===========================================================================
// Flash attention via mma.sync. CTA: 128 q-rows, 8 warps (16 rows each),
// 64-key steps. Q fragments persistent in registers; S-frags reused as
// P A-frags; softmax via quad shuffles only.
// ===========================================================================
#define AT_KSTR 72                      /* bf16 smem row stride */
#define AT_ROWB (AT_KSTR*2)             /* 144 bytes */
#define AT_MAT  (64*AT_ROWB)            /* 9216 bytes */
#define AT_SMEM (4*AT_MAT + 256)        /* K h/l, V h/l, mask */

__global__ __launch_bounds__(256, 1) void attn_mma_kernel(
    const __nv_bfloat16* __restrict__ Qh, const __nv_bfloat16* __restrict__ Ql,
    const __nv_bfloat16* __restrict__ Kh, const __nv_bfloat16* __restrict__ Kl,
    const __nv_bfloat16* __restrict__ Vh, const __nv_bfloat16* __restrict__ Vl,
    const float* __restrict__ mask, float* __restrict__ out)
{
    __shared__ __align__(16) uint8_t smem_buf[AT_SMEM];
    const uint32_t sb = smem_u32(smem_buf);
    const uint32_t KH = sb, KL = sb + AT_MAT, VH = sb + 2*AT_MAT, VL = sb + 3*AT_MAT;
    float* msk = (float*)(smem_buf + 4*AT_MAT);

    const int t   = threadIdx.x;
    const int wid = t >> 5;
    const int l   = t & 31;
    const int q0  = blockIdx.x * 128;
    const int h   = blockIdx.y;
    const int bz  = blockIdx.z;
    const int bh  = bz * NHD + h;

    const int rowin = (l & 7) + ((l >> 3) & 1) * 8;
    const int colb  = ((l >> 4) & 1) * 8;
    const int g     = l >> 2;
    const int tcol  = (l & 3) * 2;

    const size_t qoff = ((size_t)bh * SS + q0) * HD;
    const size_t koff = (size_t)bh * SS * HD;
    const size_t voff = (size_t)bh * HD * SS;

    // ---- stage Q (128 x 64, hi/lo) into smem, then ldmatrix to registers
#pragma unroll
    for (int rep = 0; rep < 8; rep++) {
        const int idx = rep * 256 + t;          // 0..2047
        const int mat = idx >> 10;              // 0: hi, 1: lo
        const int row = (idx >> 3) & 127;
        const int c   = idx & 7;                // 16B chunk
        const __nv_bfloat16* src = (mat ? Ql : Qh) + qoff + row * HD + c * 8;
        *(float4*)(smem_buf + mat * (2*AT_MAT) + row * AT_ROWB + c * 16) =
            *(const float4*)src;
    }
    __syncthreads();
    uint32_t qh[4][4], ql[4][4];
#pragma unroll
    for (int ks = 0; ks < 4; ks++) {
        const uint32_t off = (uint32_t)((wid*16 + rowin) * AT_ROWB + (colb + ks*16) * 2);
        ldm_x4(qh[ks], sb + off);
        ldm_x4(ql[ks], sb + 2*AT_MAT + off);
    }
    __syncthreads();

    float o[8][4];
#pragma unroll
    for (int dt = 0; dt < 8; dt++)
#pragma unroll
        for (int i = 0; i < 4; i++) o[dt][i] = 0.f;
    float m0r = -1e30f, m1r = -1e30f, l0r = 0.f, l1r = 0.f;

    for (int kt = 0; kt < SS / 64; kt++) {
        // ---- fill K (hi/lo) and V^T (hi/lo) tiles + mask
#pragma unroll
        for (int rep = 0; rep < 8; rep++) {
            const int idx = rep * 256 + t;      // 0..2047
            const int mat = idx >> 9;           // 0..3 : KH, KL, VH, VL
            const int row = (idx >> 3) & 63;
            const int c   = idx & 7;
            const __nv_bfloat16* src;
            if (mat == 0)      src = Kh + koff + (size_t)(kt*64 + row) * HD + c*8;
            else if (mat == 1) src = Kl + koff + (size_t)(kt*64 + row) * HD + c*8;
            else if (mat == 2) src = Vh + voff + (size_t)row * SS + kt*64 + c*8;
            else               src = Vl + voff + (size_t)row * SS + kt*64 + c*8;
            *(float4*)(smem_buf + mat * AT_MAT + row * AT_ROWB + c * 16) =
                *(const float4*)src;
        }
        if (t < 16)
            *(float4*)&msk[t*4] = *(const float4*)&mask[(size_t)bz * SS + kt*64 + t*4];
        __syncthreads();

        // ---- S = Q * K^T  (scale pre-folded into Q)
        float s[8][4];
#pragma unroll
        for (int nt = 0; nt < 8; nt++)
#pragma unroll
            for (int i = 0; i < 4; i++) s[nt][i] = 0.f;
#pragma unroll
        for (int ks = 0; ks < 4; ks++) {
#pragma unroll
            for (int np = 0; np < 4; np++) {
                uint32_t kh[4], kl[4];
                const uint32_t off = (uint32_t)((np*16 + rowin) * AT_ROWB
                                                + (colb + ks*16) * 2);
                ldm_x4(kh, KH + off);
                ldm_x4(kl, KL + off);
                const int n0t = 2*np, n1t = 2*np + 1;
                mma_bf16(s[n0t], qh[ks], kh[0], kh[2]);
                mma_bf16(s[n0t], qh[ks], kl[0], kl[2]);
                mma_bf16(s[n0t], ql[ks], kh[0], kh[2]);
                mma_bf16(s[n1t], qh[ks], kh[1], kh[3]);
                mma_bf16(s[n1t], qh[ks], kl[1], kl[3]);
                mma_bf16(s[n1t], ql[ks], kh[1], kh[3]);
            }
        }

        // ---- online softmax (rows g, g+8; quad-shuffle reductions)
        float rmax0 = -1e30f, rmax1 = -1e30f;
#pragma unroll
        for (int nt = 0; nt < 8; nt++) {
            const float2 mk = *(const float2*)&msk[nt*8 + tcol];
            s[nt][0] += mk.x; s[nt][1] += mk.y;
            s[nt][2] += mk.x; s[nt][3] += mk.y;
            rmax0 = fmaxf(rmax0, fmaxf(s[nt][0], s[nt][1]));
            rmax1 = fmaxf(rmax1, fmaxf(s[nt][2], s[nt][3]));
        }
        rmax0 = fmaxf(rmax0, __shfl_xor_sync(0xFFFFFFFF, rmax0, 1));
        rmax0 = fmaxf(rmax0, __shfl_xor_sync(0xFFFFFFFF, rmax0, 2));
        rmax1 = fmaxf(rmax1, __shfl_xor_sync(0xFFFFFFFF, rmax1, 1));
        rmax1 = fmaxf(rmax1, __shfl_xor_sync(0xFFFFFFFF, rmax1, 2));
        const float mn0 = fmaxf(m0r, rmax0), mn1 = fmaxf(m1r, rmax1);
        const float f0 = __expf(m0r - mn0), f1 = __expf(m1r - mn1);
        m0r = mn0; m1r = mn1;
        float rs0 = 0.f, rs1 = 0.f;
#pragma unroll
        for (int nt = 0; nt < 8; nt++) {
            s[nt][0] = __expf(s[nt][0] - mn0);
            s[nt][1] = __expf(s[nt][1] - mn0);
            s[nt][2] = __expf(s[nt][2] - mn1);
            s[nt][3] = __expf(s[nt][3] - mn1);
            rs0 += s[nt][0] + s[nt][1];
            rs1 += s[nt][2] + s[nt][3];
        }
        rs0 += __shfl_xor_sync(0xFFFFFFFF, rs0, 1);
        rs0 += __shfl_xor_sync(0xFFFFFFFF, rs0, 2);
        rs1 += __shfl_xor_sync(0xFFFFFFFF, rs1, 1);
        rs1 += __shfl_xor_sync(0xFFFFFFFF, rs1, 2);
        l0r = l0r * f0 + rs0;
        l1r = l1r * f1 + rs1;
#pragma unroll
        for (int dt = 0; dt < 8; dt++) {
            o[dt][0] *= f0; o[dt][1] *= f0;
            o[dt][2] *= f1; o[dt][3] *= f1;
        }

        // ---- pack P into bf16 hi/lo A-fragments
        uint32_t ph[4][4], pl[4][4];
#pragma unroll
        for (int ks = 0; ks < 4; ks++) {
            split2(s[2*ks][0],   s[2*ks][1],   ph[ks][0], pl[ks][0]);
            split2(s[2*ks][2],   s[2*ks][3],   ph[ks][1], pl[ks][1]);
            split2(s[2*ks+1][0], s[2*ks+1][1], ph[ks][2], pl[ks][2]);
            split2(s[2*ks+1][2], s[2*ks+1][3], ph[ks][3], pl[ks][3]);
        }

        // ---- O += P * V   (B-frags from V^T [d][kt])
#pragma unroll
        for (int ks = 0; ks < 4; ks++) {
#pragma unroll
            for (int dp = 0; dp < 4; dp++) {
                uint32_t vh[4], vl[4];
                const uint32_t off = (uint32_t)((dp*16 + rowin) * AT_ROWB
                                                + (colb + ks*16) * 2);
                ldm_x4(vh, VH + off);
                ldm_x4(vl, VL + off);
                const int d0 = 2*dp, d1 = 2*dp + 1;
                mma_bf16(o[d0], ph[ks], vh[0], vh[2]);
                mma_bf16(o[d0], pl[ks], vh[0], vh[2]);
                mma_bf16(o[d0], ph[ks], vl[0], vl[2]);
                mma_bf16(o[d1], ph[ks], vh[1], vh[3]);
                mma_bf16(o[d1], pl[ks], vh[1], vh[3]);
                mma_bf16(o[d1], ph[ks], vl[1], vl[3]);
            }
        }
        __syncthreads();   // all smem reads done before next fill
    }

    // ---- finalize: O /= l, store fp32 [b, s, h*64 + d]
    const float inv0 = 1.f / l0r, inv1 = 1.f / l1r;
    const int s0 = q0 + wid * 16 + g;
#pragma unroll
    for (int dt = 0; dt < 8; dt++) {
        const int col = h * HD + dt * 8 + tcol;
        float2 r0; r0.x = o[dt][0] * inv0; r0.y = o[dt][1] * inv0;
        float2 r1; r1.x = o[dt][2] * inv1; r1.y = o[dt][3] * inv1;
        *(float2*)&out[(size_t)(bz * SS + s0)     * HH + col] = r0;
        *(float2*)&out[(size_t)(bz * SS + s0 + 8) * HH + col] = r1;
    }
}

// ---------------------------------------------------------------------------
extern "C" void kernel_launch(void* const* d_in, const int* in_sizes, int n_in,
                              void* d_out, int out_size)
{
    const float* query = (const float*)d_in[0];
    const float* key   = (const float*)d_in[1];
    const float* value = (const float*)d_in[2];
    const float* amask = (const float*)d_in[3];
    const float* Wq    = (const float*)d_in[4];
    const float* bq    = (const float*)d_in[5];
    const float* Wk    = (const float*)d_in[6];
    const float* bk    = (const float*)d_in[7];
    const float* Wv    = (const float*)d_in[8];
    const float* bv    = (const float*)d_in[9];
    float* out = (float*)d_out;

    __nv_bfloat16 *qh, *ql, *kh, *kl, *vh, *vl;
    cudaGetSymbolAddress((void**)&qh, g_Qh);
    cudaGetSymbolAddress((void**)&ql, g_Ql);
    cudaGetSymbolAddress((void**)&kh, g_Kh);
    cudaGetSymbolAddress((void**)&kl, g_Kl);
    cudaGetSymbolAddress((void**)&vh, g_Vh);
    cudaGetSymbolAddress((void**)&vl, g_Vl);

    // Q, K: standard orientation (X rows = m). V: swapped (features = m) so the
    // transposed [b,h,d,s] store is coalesced along s.
    dim3 gq(HH / 128, MM / 128);   // (8, 32)
    dim3 gv(MM / 128, HH / 128);   // (32, 8)
    proj_mma_kernel<0><<<gq, 256>>>(query, Wq, bq, qh, ql, 0.125f);
    proj_mma_kernel<0><<<gq, 256>>>(key,   Wk, bk, kh, kl, 1.0f);
    proj_mma_kernel<1><<<gv, 256>>>(Wv, value, bv, vh, vl, 1.0f);

    dim3 ag(SS / 128, NHD, BB);    // (16, 16, 2)
    attn_mma_kernel<<<ag, 256>>>(qh, ql, kh, kl, vh, vl, amask, out);
}

// round 9
// speedup vs baseline: 2.9644x; 1.2942x over previous
#include <cuda_runtime.h>
#include <cuda_bf16.h>
#include <stdint.h>
#include <stddef.h>

#define BB 2
#define SS 2048
#define HH 1024
#define NHD 16
#define HD 64
#define MM (BB*SS)   /* 4096 */

// ---- split inputs (hi/lo bf16), filled by split_kernel --------------------
__device__ __align__(16) __nv_bfloat16 g_Xh[3u*MM*HH];
__device__ __align__(16) __nv_bfloat16 g_Xl[3u*MM*HH];
__device__ __align__(16) __nv_bfloat16 g_Wh[3u*HH*HH];
__device__ __align__(16) __nv_bfloat16 g_Wl[3u*HH*HH];

// ---- projected tensors, pre-split bf16 (value ~= hi + lo) -----------------
// Q, K: [b, h, s, d] row-major.   V: [b, h, d, s] (transposed).
__device__ __align__(16) __nv_bfloat16 g_Qh[MM*HH];
__device__ __align__(16) __nv_bfloat16 g_Ql[MM*HH];
__device__ __align__(16) __nv_bfloat16 g_Kh[MM*HH];
__device__ __align__(16) __nv_bfloat16 g_Kl[MM*HH];
__device__ __align__(16) __nv_bfloat16 g_Vh[MM*HH];
__device__ __align__(16) __nv_bfloat16 g_Vl[MM*HH];

// ---------------------------------------------------------------------------
// helpers
// ---------------------------------------------------------------------------
__device__ __forceinline__ uint32_t smem_u32(const void* p) {
    uint32_t a;
    asm("{ .reg .u64 t; cvta.to.shared.u64 t, %1; cvt.u32.u64 %0, t; }"
        : "=r"(a) : "l"(p));
    return a;
}

__device__ __forceinline__ void split2(float x, float y, uint32_t& h, uint32_t& l) {
    __nv_bfloat162 hh = __floats2bfloat162_rn(x, y);
    float2 hf = __bfloat1622float2(hh);
    __nv_bfloat162 ll = __floats2bfloat162_rn(x - hf.x, y - hf.y);
    h = *reinterpret_cast<uint32_t*>(&hh);
    l = *reinterpret_cast<uint32_t*>(&ll);
}

__device__ __forceinline__ void ldm_x4(uint32_t r[4], uint32_t addr) {
    asm volatile("ldmatrix.sync.aligned.m8n8.x4.shared.b16 {%0,%1,%2,%3}, [%4];"
                 : "=r"(r[0]), "=r"(r[1]), "=r"(r[2]), "=r"(r[3]) : "r"(addr));
}

__device__ __forceinline__ void mma_bf16(float c[4], const uint32_t a[4],
                                         uint32_t b0, uint32_t b1) {
    asm volatile("mma.sync.aligned.m16n8k16.row.col.f32.bf16.bf16.f32 "
                 "{%0,%1,%2,%3}, {%4,%5,%6,%7}, {%8,%9}, {%0,%1,%2,%3};"
                 : "+f"(c[0]), "+f"(c[1]), "+f"(c[2]), "+f"(c[3])
                 : "r"(a[0]), "r"(a[1]), "r"(a[2]), "r"(a[3]), "r"(b0), "r"(b1));
}

#define CP_ASYNC16(dst, src) \
    asm volatile("cp.async.cg.shared.global [%0], [%1], 16;" \
                 :: "r"(dst), "l"(src) : "memory")
#define CP_COMMIT()  asm volatile("cp.async.commit_group;" ::: "memory")
#define CP_WAIT0()   asm volatile("cp.async.wait_group 0;" ::: "memory")

// ===========================================================================
// split_kernel: fp32 -> (hi bf16, lo bf16), vectorized float4
// ===========================================================================
__global__ __launch_bounds__(256) void split_kernel(
    const float* __restrict__ in, __nv_bfloat16* __restrict__ hi,
    __nv_bfloat16* __restrict__ lo, int n4)
{
    int i = blockIdx.x * blockDim.x + threadIdx.x;
    if (i < n4) {
        float4 f = ((const float4*)in)[i];
        uint32_t h0, h1, l0, l1;
        split2(f.x, f.y, h0, l0);
        split2(f.z, f.w, h1, l1);
        ((uint2*)hi)[i] = make_uint2(h0, h1);
        ((uint2*)lo)[i] = make_uint2(l0, l1);
    }
}

// ===========================================================================
// Projection GEMM via mma.sync, bf16x3 split, cp.async 2-stage pipeline.
//   C[m,n] = sum_k A[m,k]*B[n,k]   (A, B pre-split bf16, K contiguous)
// MODE 0 (Q/K): out = (C + bias[n]) * scale, split hi/lo, stored [b,h,s,d].
// MODE 1 (V):   A = W, B = X -> C = (X@W^T)^T, stored [b,h,d,s], bias[m-row].
// CTA 128x128, BK=64, 8 warps (warp tile 64x32).
// ===========================================================================
#define PJ_ROWB 144                      /* bytes per smem row (128 data + pad) */
#define PJ_MAT  (128*PJ_ROWB)            /* 18432 */
#define PJ_STG  (4*PJ_MAT)               /* 73728: AH, AL, BH, BL */
#define PJ_SMEM (2*PJ_STG)               /* 147456 */

template <int MODE>
__global__ __launch_bounds__(256, 1) void proj_mma_kernel(
    const __nv_bfloat16* __restrict__ Ah, const __nv_bfloat16* __restrict__ Al,
    const __nv_bfloat16* __restrict__ Bh, const __nv_bfloat16* __restrict__ Bl,
    const float* __restrict__ bias,
    __nv_bfloat16* __restrict__ outH, __nv_bfloat16* __restrict__ outL,
    float scale)
{
    extern __shared__ __align__(16) uint8_t psm[];
    const uint32_t sb = smem_u32(psm);

    const int t   = threadIdx.x;
    const int wid = t >> 5;
    const int l   = t & 31;
    const int m0  = blockIdx.y * 128;
    const int n0  = blockIdx.x * 128;
    const int wm0 = (wid & 1) * 64;
    const int wn0 = (wid >> 1) * 32;

    const int rowin = (l & 7) + ((l >> 3) & 1) * 8;
    const int colb  = ((l >> 4) & 1) * 8;

    // per-thread cp.async geometry (16 chunks/thread/stage)
    const __nv_bfloat16* srcs[4] = { Ah, Al, Bh, Bl };

    float acc[4][4][4];
#pragma unroll
    for (int mt = 0; mt < 4; mt++)
#pragma unroll
        for (int nt = 0; nt < 4; nt++)
#pragma unroll
            for (int i = 0; i < 4; i++) acc[mt][nt][i] = 0.f;

    // ---- issue one stage of cp.asyncs
    auto issue = [&](int kt, uint32_t base) {
        const int k0 = kt * 64;
#pragma unroll
        for (int rep = 0; rep < 16; rep++) {
            const int idx = rep * 256 + t;          // 0..4095
            const int mat = idx >> 10;              // 0..3
            const int row = (idx >> 3) & 127;
            const int c   = idx & 7;
            const int grow = (mat < 2 ? m0 : n0) + row;
            const __nv_bfloat16* src = srcs[mat] + (size_t)grow * HH + k0 + c * 8;
            CP_ASYNC16(base + mat * PJ_MAT + row * PJ_ROWB + c * 16, src);
        }
    };

    issue(0, sb);
    CP_COMMIT();

    for (int kt = 0; kt < HH / 64; kt++) {          // 16 iterations
        const uint32_t cur = sb + (kt & 1) * PJ_STG;
        CP_WAIT0();
        __syncthreads();
        if (kt + 1 < HH / 64) {
            issue(kt + 1, sb + ((kt + 1) & 1) * PJ_STG);
            CP_COMMIT();
        }

        const uint32_t AH = cur, AL = cur + PJ_MAT, BH = cur + 2*PJ_MAT, BL = cur + 3*PJ_MAT;
#pragma unroll
        for (int ks = 0; ks < 4; ks++) {
            uint32_t ah[4][4], al[4][4];
#pragma unroll
            for (int mt = 0; mt < 4; mt++) {
                const uint32_t off = (uint32_t)((wm0 + mt*16 + rowin) * PJ_ROWB
                                                + (colb + ks*16) * 2);
                ldm_x4(ah[mt], AH + off);
                ldm_x4(al[mt], AL + off);
            }
            uint32_t bh[4][2], bl[4][2];
#pragma unroll
            for (int np = 0; np < 2; np++) {
                uint32_t r[4];
                const uint32_t off = (uint32_t)((wn0 + np*16 + rowin) * PJ_ROWB
                                                + (colb + ks*16) * 2);
                ldm_x4(r, BH + off);
                bh[2*np][0] = r[0]; bh[2*np][1] = r[2];
                bh[2*np+1][0] = r[1]; bh[2*np+1][1] = r[3];
                ldm_x4(r, BL + off);
                bl[2*np][0] = r[0]; bl[2*np][1] = r[2];
                bl[2*np+1][0] = r[1]; bl[2*np+1][1] = r[3];
            }
#pragma unroll
            for (int mt = 0; mt < 4; mt++)
#pragma unroll
                for (int nt = 0; nt < 4; nt++) {
                    mma_bf16(acc[mt][nt], ah[mt], bh[nt][0], bh[nt][1]);
                    mma_bf16(acc[mt][nt], ah[mt], bl[nt][0], bl[nt][1]);
                    mma_bf16(acc[mt][nt], al[mt], bh[nt][0], bh[nt][1]);
                }
        }
    }

    // ---- epilogue
    const int g    = l >> 2;
    const int tcol = (l & 3) * 2;
#pragma unroll
    for (int mt = 0; mt < 4; mt++) {
#pragma unroll
        for (int nt = 0; nt < 4; nt++) {
            const int gm = m0 + wm0 + mt * 16 + g;
            const int gn = n0 + wn0 + nt * 8 + tcol;
            if (MODE == 0) {
                const float b0 = __ldg(&bias[gn]), b1 = __ldg(&bias[gn + 1]);
                const int head = gn >> 6, d = gn & 63;
#pragma unroll
                for (int i = 0; i < 2; i++) {
                    const int m = gm + i * 8;
                    const int bb = m >> 11, s = m & 2047;
                    uint32_t hw, lw;
                    split2((acc[mt][nt][2*i]   + b0) * scale,
                           (acc[mt][nt][2*i+1] + b1) * scale, hw, lw);
                    const size_t off = ((size_t)(bb * NHD + head) * SS + s) * HD + d;
                    *(uint32_t*)&outH[off] = hw;
                    *(uint32_t*)&outL[off] = lw;
                }
            } else {
                const int bb = gn >> 11, s = gn & 2047;
#pragma unroll
                for (int i = 0; i < 2; i++) {
                    const int feat = gm + i * 8;
                    const float br = __ldg(&bias[feat]);
                    const int head = feat >> 6, d = feat & 63;
                    uint32_t hw, lw;
                    split2((acc[mt][nt][2*i]   + br) * scale,
                           (acc[mt][nt][2*i+1] + br) * scale, hw, lw);
                    const size_t off = ((size_t)(bb * NHD + head) * HD + d) * SS + s;
                    *(uint32_t*)&outH[off] = hw;
                    *(uint32_t*)&outL[off] = lw;
                }
            }
        }
    }
}

// ===========================================================================
// Flash attention via mma.sync + cp.async 2-stage pipeline.
// CTA: 64 q-rows, 4 warps (16 rows each) -> 2 CTAs/SM. 64-key steps.
// Q fragments persistent; softmax quad-shuffle only.
// ===========================================================================
#define AT_ROWB 144
#define AT_MAT  (64*AT_ROWB)             /* 9216 */
#define AT_STG  (4*AT_MAT + 256)         /* 37120: KH, KL, VH, VL, mask */
#define AT_SMEM (2*AT_STG)               /* 74240 */

__global__ __launch_bounds__(128, 1) void attn_mma_kernel(
    const __nv_bfloat16* __restrict__ Qh, const __nv_bfloat16* __restrict__ Ql,
    const __nv_bfloat16* __restrict__ Kh, const __nv_bfloat16* __restrict__ Kl,
    const __nv_bfloat16* __restrict__ Vh, const __nv_bfloat16* __restrict__ Vl,
    const float* __restrict__ mask, float* __restrict__ out)
{
    extern __shared__ __align__(16) uint8_t smem_buf[];
    const uint32_t sb = smem_u32(smem_buf);

    const int t   = threadIdx.x;
    const int wid = t >> 5;
    const int l   = t & 31;
    const int q0  = blockIdx.x * 64;
    const int h   = blockIdx.y;
    const int bz  = blockIdx.z;
    const int bh  = bz * NHD + h;

    const int rowin = (l & 7) + ((l >> 3) & 1) * 8;
    const int colb  = ((l >> 4) & 1) * 8;
    const int g     = l >> 2;
    const int tcol  = (l & 3) * 2;

    const size_t qoff = ((size_t)bh * SS + q0) * HD;
    const size_t koff = (size_t)bh * SS * HD;
    const size_t voff = (size_t)bh * HD * SS;
    const float* mrow_g = mask + (size_t)bz * SS;

    // ---- stage Q (64 x 64, hi/lo) through buffer 0 via cp.async
#pragma unroll
    for (int rep = 0; rep < 8; rep++) {
        const int idx = rep * 128 + t;          // 0..1023
        const int mat = idx >> 9;               // 0: hi, 1: lo
        const int row = (idx >> 3) & 63;
        const int c   = idx & 7;
        const __nv_bfloat16* src = (mat ? Ql : Qh) + qoff + row * HD + c * 8;
        CP_ASYNC16(sb + mat * AT_MAT + row * AT_ROWB + c * 16, src);
    }
    CP_COMMIT();
    CP_WAIT0();
    __syncthreads();
    uint32_t qh[4][4], ql[4][4];
#pragma unroll
    for (int ks = 0; ks < 4; ks++) {
        const uint32_t off = (uint32_t)((wid*16 + rowin) * AT_ROWB + (colb + ks*16) * 2);
        ldm_x4(qh[ks], sb + off);
        ldm_x4(ql[ks], sb + AT_MAT + off);
    }
    __syncthreads();    // done reading buf0 before KV overwrite

    // ---- KV stage issuer
    auto issue_kv = [&](int kt, uint32_t base) {
#pragma unroll
        for (int rep = 0; rep < 16; rep++) {
            const int idx = rep * 128 + t;      // 0..2047
            const int mat = idx >> 9;           // 0..3 : KH, KL, VH, VL
            const int row = (idx >> 3) & 63;
            const int c   = idx & 7;
            const __nv_bfloat16* src;
            if (mat == 0)      src = Kh + koff + (size_t)(kt*64 + row) * HD + c*8;
            else if (mat == 1) src = Kl + koff + (size_t)(kt*64 + row) * HD + c*8;
            else if (mat == 2) src = Vh + voff + (size_t)row * SS + kt*64 + c*8;
            else               src = Vl + voff + (size_t)row * SS + kt*64 + c*8;
            CP_ASYNC16(base + mat * AT_MAT + row * AT_ROWB + c * 16, src);
        }
        if (t < 16)
            CP_ASYNC16(base + 4*AT_MAT + t*16, mrow_g + kt*64 + t*4);
    };

    float o[8][4];
#pragma unroll
    for (int dt = 0; dt < 8; dt++)
#pragma unroll
        for (int i = 0; i < 4; i++) o[dt][i] = 0.f;
    float m0r = -1e30f, m1r = -1e30f, l0r = 0.f, l1r = 0.f;

    issue_kv(0, sb);
    CP_COMMIT();

    for (int kt = 0; kt < SS / 64; kt++) {
        const uint32_t cur = sb + (kt & 1) * AT_STG;
        CP_WAIT0();
        __syncthreads();
        if (kt + 1 < SS / 64) {
            issue_kv(kt + 1, sb + ((kt + 1) & 1) * AT_STG);
            CP_COMMIT();
        }

        const uint32_t KH = cur, KL = cur + AT_MAT, VH = cur + 2*AT_MAT, VL = cur + 3*AT_MAT;
        const float* msk = (const float*)(smem_buf + (kt & 1) * AT_STG + 4*AT_MAT);

        // ---- S = Q * K^T
        float s[8][4];
#pragma unroll
        for (int nt = 0; nt < 8; nt++)
#pragma unroll
            for (int i = 0; i < 4; i++) s[nt][i] = 0.f;
#pragma unroll
        for (int ks = 0; ks < 4; ks++) {
#pragma unroll
            for (int np = 0; np < 4; np++) {
                uint32_t kh[4], kl[4];
                const uint32_t off = (uint32_t)((np*16 + rowin) * AT_ROWB
                                                + (colb + ks*16) * 2);
                ldm_x4(kh, KH + off);
                ldm_x4(kl, KL + off);
                const int n0t = 2*np, n1t = 2*np + 1;
                mma_bf16(s[n0t], qh[ks], kh[0], kh[2]);
                mma_bf16(s[n0t], qh[ks], kl[0], kl[2]);
                mma_bf16(s[n0t], ql[ks], kh[0], kh[2]);
                mma_bf16(s[n1t], qh[ks], kh[1], kh[3]);
                mma_bf16(s[n1t], qh[ks], kl[1], kl[3]);
                mma_bf16(s[n1t], ql[ks], kh[1], kh[3]);
            }
        }

        // ---- online softmax
        float rmax0 = -1e30f, rmax1 = -1e30f;
#pragma unroll
        for (int nt = 0; nt < 8; nt++) {
            const float2 mk = *(const float2*)&msk[nt*8 + tcol];
            s[nt][0] += mk.x; s[nt][1] += mk.y;
            s[nt][2] += mk.x; s[nt][3] += mk.y;
            rmax0 = fmaxf(rmax0, fmaxf(s[nt][0], s[nt][1]));
            rmax1 = fmaxf(rmax1, fmaxf(s[nt][2], s[nt][3]));
        }
        rmax0 = fmaxf(rmax0, __shfl_xor_sync(0xFFFFFFFF, rmax0, 1));
        rmax0 = fmaxf(rmax0, __shfl_xor_sync(0xFFFFFFFF, rmax0, 2));
        rmax1 = fmaxf(rmax1, __shfl_xor_sync(0xFFFFFFFF, rmax1, 1));
        rmax1 = fmaxf(rmax1, __shfl_xor_sync(0xFFFFFFFF, rmax1, 2));
        const float mn0 = fmaxf(m0r, rmax0), mn1 = fmaxf(m1r, rmax1);
        const float f0 = __expf(m0r - mn0), f1 = __expf(m1r - mn1);
        m0r = mn0; m1r = mn1;
        float rs0 = 0.f, rs1 = 0.f;
#pragma unroll
        for (int nt = 0; nt < 8; nt++) {
            s[nt][0] = __expf(s[nt][0] - mn0);
            s[nt][1] = __expf(s[nt][1] - mn0);
            s[nt][2] = __expf(s[nt][2] - mn1);
            s[nt][3] = __expf(s[nt][3] - mn1);
            rs0 += s[nt][0] + s[nt][1];
            rs1 += s[nt][2] + s[nt][3];
        }
        rs0 += __shfl_xor_sync(0xFFFFFFFF, rs0, 1);
        rs0 += __shfl_xor_sync(0xFFFFFFFF, rs0, 2);
        rs1 += __shfl_xor_sync(0xFFFFFFFF, rs1, 1);
        rs1 += __shfl_xor_sync(0xFFFFFFFF, rs1, 2);
        l0r = l0r * f0 + rs0;
        l1r = l1r * f1 + rs1;
#pragma unroll
        for (int dt = 0; dt < 8; dt++) {
            o[dt][0] *= f0; o[dt][1] *= f0;
            o[dt][2] *= f1; o[dt][3] *= f1;
        }

        // ---- pack P into bf16 hi/lo A-fragments
        uint32_t ph[4][4], pl[4][4];
#pragma unroll
        for (int ks = 0; ks < 4; ks++) {
            split2(s[2*ks][0],   s[2*ks][1],   ph[ks][0], pl[ks][0]);
            split2(s[2*ks][2],   s[2*ks][3],   ph[ks][1], pl[ks][1]);
            split2(s[2*ks+1][0], s[2*ks+1][1], ph[ks][2], pl[ks][2]);
            split2(s[2*ks+1][2], s[2*ks+1][3], ph[ks][3], pl[ks][3]);
        }

        // ---- O += P * V
#pragma unroll
        for (int ks = 0; ks < 4; ks++) {
#pragma unroll
            for (int dp = 0; dp < 4; dp++) {
                uint32_t vh[4], vl[4];
                const uint32_t off = (uint32_t)((dp*16 + rowin) * AT_ROWB
                                                + (colb + ks*16) * 2);
                ldm_x4(vh, VH + off);
                ldm_x4(vl, VL + off);
                const int d0 = 2*dp, d1 = 2*dp + 1;
                mma_bf16(o[d0], ph[ks], vh[0], vh[2]);
                mma_bf16(o[d0], pl[ks], vh[0], vh[2]);
                mma_bf16(o[d0], ph[ks], vl[0], vl[2]);
                mma_bf16(o[d1], ph[ks], vh[1], vh[3]);
                mma_bf16(o[d1], pl[ks], vh[1], vh[3]);
                mma_bf16(o[d1], ph[ks], vl[1], vl[3]);
            }
        }
    }

    // ---- finalize
    const float inv0 = 1.f / l0r, inv1 = 1.f / l1r;
    const int s0 = q0 + wid * 16 + g;
#pragma unroll
    for (int dt = 0; dt < 8; dt++) {
        const int col = h * HD + dt * 8 + tcol;
        float2 r0; r0.x = o[dt][0] * inv0; r0.y = o[dt][1] * inv0;
        float2 r1; r1.x = o[dt][2] * inv1; r1.y = o[dt][3] * inv1;
        *(float2*)&out[(size_t)(bz * SS + s0)     * HH + col] = r0;
        *(float2*)&out[(size_t)(bz * SS + s0 + 8) * HH + col] = r1;
    }
}

// ---------------------------------------------------------------------------
extern "C" void kernel_launch(void* const* d_in, const int* in_sizes, int n_in,
                              void* d_out, int out_size)
{
    const float* query = (const float*)d_in[0];
    const float* key   = (const float*)d_in[1];
    const float* value = (const float*)d_in[2];
    const float* amask = (const float*)d_in[3];
    const float* Wq    = (const float*)d_in[4];
    const float* bq    = (const float*)d_in[5];
    const float* Wk    = (const float*)d_in[6];
    const float* bk    = (const float*)d_in[7];
    const float* Wv    = (const float*)d_in[8];
    const float* bv    = (const float*)d_in[9];
    float* out = (float*)d_out;

    __nv_bfloat16 *xh, *xl, *wh, *wl;
    __nv_bfloat16 *qh, *ql, *kh, *kl, *vh, *vl;
    cudaGetSymbolAddress((void**)&xh, g_Xh);
    cudaGetSymbolAddress((void**)&xl, g_Xl);
    cudaGetSymbolAddress((void**)&wh, g_Wh);
    cudaGetSymbolAddress((void**)&wl, g_Wl);
    cudaGetSymbolAddress((void**)&qh, g_Qh);
    cudaGetSymbolAddress((void**)&ql, g_Ql);
    cudaGetSymbolAddress((void**)&kh, g_Kh);
    cudaGetSymbolAddress((void**)&kl, g_Kl);
    cudaGetSymbolAddress((void**)&vh, g_Vh);
    cudaGetSymbolAddress((void**)&vl, g_Vl);

    cudaFuncSetAttribute(proj_mma_kernel<0>,
                         cudaFuncAttributeMaxDynamicSharedMemorySize, PJ_SMEM);
    cudaFuncSetAttribute(proj_mma_kernel<1>,
                         cudaFuncAttributeMaxDynamicSharedMemorySize, PJ_SMEM);
    cudaFuncSetAttribute(attn_mma_kernel,
                         cudaFuncAttributeMaxDynamicSharedMemorySize, AT_SMEM);

    // ---- split inputs to bf16 hi/lo
    const int nx4 = MM * HH / 4;      // 1M float4
    const int nw4 = HH * HH / 4;      // 256K float4
    split_kernel<<<(nx4 + 255)/256, 256>>>(query, xh,            xl,            nx4);
    split_kernel<<<(nx4 + 255)/256, 256>>>(key,   xh + (size_t)MM*HH,   xl + (size_t)MM*HH,   nx4);
    split_kernel<<<(nx4 + 255)/256, 256>>>(value, xh + (size_t)2*MM*HH, xl + (size_t)2*MM*HH, nx4);
    split_kernel<<<(nw4 + 255)/256, 256>>>(Wq, wh,                wl,                nw4);
    split_kernel<<<(nw4 + 255)/256, 256>>>(Wk, wh + (size_t)HH*HH,   wl + (size_t)HH*HH,   nw4);
    split_kernel<<<(nw4 + 255)/256, 256>>>(Wv, wh + (size_t)2*HH*HH, wl + (size_t)2*HH*HH, nw4);

    // ---- projections
    dim3 gq(HH / 128, MM / 128);   // (8, 32)
    dim3 gv(MM / 128, HH / 128);   // (32, 8)
    proj_mma_kernel<0><<<gq, 256, PJ_SMEM>>>(
        xh, xl, wh, wl, bq, qh, ql, 0.125f);
    proj_mma_kernel<0><<<gq, 256, PJ_SMEM>>>(
        xh + (size_t)MM*HH, xl + (size_t)MM*HH,
        wh + (size_t)HH*HH, wl + (size_t)HH*HH, bk, kh, kl, 1.0f);
    proj_mma_kernel<1><<<gv, 256, PJ_SMEM>>>(
        wh + (size_t)2*HH*HH, wl + (size_t)2*HH*HH,
        xh + (size_t)2*MM*HH, xl + (size_t)2*MM*HH, bv, vh, vl, 1.0f);

    // ---- attention
    dim3 ag(SS / 64, NHD, BB);     // (32, 16, 2) = 1024 CTAs
    attn_mma_kernel<<<ag, 128, AT_SMEM>>>(qh, ql, kh, kl, vh, vl, amask, out);
}

// round 10
// speedup vs baseline: 3.1961x; 1.0782x over previous
#include <cuda_runtime.h>
#include <cuda_bf16.h>
#include <stdint.h>
#include <stddef.h>

#define BB 2
#define SS 2048
#define HH 1024
#define NHD 16
#define HD 64
#define MM (BB*SS)   /* 4096 */

// ---- split inputs (hi/lo bf16) --------------------------------------------
__device__ __align__(16) __nv_bfloat16 g_Xh[3u*MM*HH];
__device__ __align__(16) __nv_bfloat16 g_Xl[3u*MM*HH];
__device__ __align__(16) __nv_bfloat16 g_Wh[3u*HH*HH];
__device__ __align__(16) __nv_bfloat16 g_Wl[3u*HH*HH];

// ---- projected tensors, pre-split bf16 ------------------------------------
// Q, K: [b, h, s, d] row-major.   V: [b, h, d, s] (transposed).
__device__ __align__(16) __nv_bfloat16 g_Qh[MM*HH];
__device__ __align__(16) __nv_bfloat16 g_Ql[MM*HH];
__device__ __align__(16) __nv_bfloat16 g_Kh[MM*HH];
__device__ __align__(16) __nv_bfloat16 g_Kl[MM*HH];
__device__ __align__(16) __nv_bfloat16 g_Vh[MM*HH];
__device__ __align__(16) __nv_bfloat16 g_Vl[MM*HH];

// ---------------------------------------------------------------------------
// helpers
// ---------------------------------------------------------------------------
__device__ __forceinline__ uint32_t smem_u32(const void* p) {
    uint32_t a;
    asm("{ .reg .u64 t; cvta.to.shared.u64 t, %1; cvt.u32.u64 %0, t; }"
        : "=r"(a) : "l"(p));
    return a;
}

__device__ __forceinline__ void split2(float x, float y, uint32_t& h, uint32_t& l) {
    __nv_bfloat162 hh = __floats2bfloat162_rn(x, y);
    float2 hf = __bfloat1622float2(hh);
    __nv_bfloat162 ll = __floats2bfloat162_rn(x - hf.x, y - hf.y);
    h = *reinterpret_cast<uint32_t*>(&hh);
    l = *reinterpret_cast<uint32_t*>(&ll);
}

__device__ __forceinline__ void ldm_x4(uint32_t r[4], uint32_t addr) {
    asm volatile("ldmatrix.sync.aligned.m8n8.x4.shared.b16 {%0,%1,%2,%3}, [%4];"
                 : "=r"(r[0]), "=r"(r[1]), "=r"(r[2]), "=r"(r[3]) : "r"(addr));
}

__device__ __forceinline__ void mma_bf16(float c[4], const uint32_t a[4],
                                         uint32_t b0, uint32_t b1) {
    asm volatile("mma.sync.aligned.m16n8k16.row.col.f32.bf16.bf16.f32 "
                 "{%0,%1,%2,%3}, {%4,%5,%6,%7}, {%8,%9}, {%0,%1,%2,%3};"
                 : "+f"(c[0]), "+f"(c[1]), "+f"(c[2]), "+f"(c[3])
                 : "r"(a[0]), "r"(a[1]), "r"(a[2]), "r"(a[3]), "r"(b0), "r"(b1));
}

#define CP_ASYNC16(dst, src) \
    asm volatile("cp.async.cg.shared.global [%0], [%1], 16;" \
                 :: "r"(dst), "l"(src) : "memory")
#define CP_COMMIT()  asm volatile("cp.async.commit_group;" ::: "memory")
#define CP_WAIT0()   asm volatile("cp.async.wait_group 0;" ::: "memory")

// ===========================================================================
// fused split kernel: 6 segments via blockIdx.y
// ===========================================================================
__global__ __launch_bounds__(256) void split6_kernel(
    const float* __restrict__ q, const float* __restrict__ k,
    const float* __restrict__ v, const float* __restrict__ wq,
    const float* __restrict__ wk, const float* __restrict__ wv)
{
    const int seg = blockIdx.y;
    const float* in;
    __nv_bfloat16 *hi, *lo;
    int n4;
    const size_t XS = (size_t)MM * HH, WS = (size_t)HH * HH;
    switch (seg) {
        case 0: in = q;  hi = g_Xh;        lo = g_Xl;        n4 = MM*HH/4; break;
        case 1: in = k;  hi = g_Xh + XS;   lo = g_Xl + XS;   n4 = MM*HH/4; break;
        case 2: in = v;  hi = g_Xh + 2*XS; lo = g_Xl + 2*XS; n4 = MM*HH/4; break;
        case 3: in = wq; hi = g_Wh;        lo = g_Wl;        n4 = HH*HH/4; break;
        case 4: in = wk; hi = g_Wh + WS;   lo = g_Wl + WS;   n4 = HH*HH/4; break;
        default:in = wv; hi = g_Wh + 2*WS; lo = g_Wl + 2*WS; n4 = HH*HH/4; break;
    }
    const int stride = gridDim.x * blockDim.x;
    for (int i = blockIdx.x * blockDim.x + threadIdx.x; i < n4; i += stride) {
        float4 f = ((const float4*)in)[i];
        uint32_t h0, h1, l0, l1;
        split2(f.x, f.y, h0, l0);
        split2(f.z, f.w, h1, l1);
        ((uint2*)hi)[i] = make_uint2(h0, h1);
        ((uint2*)lo)[i] = make_uint2(l0, l1);
    }
}

// ===========================================================================
// Fused projection GEMM (Q, K, V via blockIdx.z), mma.sync bf16x3,
// cp.async 2-stage. CTA 128x128, BK=64, 512 threads, warp tile 32x32.
//   z=0,1 (Q,K): C[m,n] = X[m,:]·W[n,:]; out=(C+bias[n])*scale -> [b,h,s,d]
//   z=2   (V):   A=W, B=X -> C=(X@W^T)^T; out stored [b,h,d,s], bias[m-row]
// ===========================================================================
#define PJ_ROWB 144                      /* 128B data + 16B pad */
#define PJ_MAT  (128*PJ_ROWB)            /* 18432 */
#define PJ_STG  (4*PJ_MAT)               /* 73728: AH, AL, BH, BL */
#define PJ_SMEM (2*PJ_STG)               /* 147456 */

__global__ __launch_bounds__(512, 1) void proj3_kernel(
    const float* __restrict__ bq, const float* __restrict__ bk,
    const float* __restrict__ bv)
{
    extern __shared__ __align__(16) uint8_t psm[];
    const uint32_t sb = smem_u32(psm);

    const int z   = blockIdx.z;
    const int t   = threadIdx.x;
    const int wid = t >> 5;
    const int l   = t & 31;

    const size_t XS = (size_t)MM * HH, WS = (size_t)HH * HH;
    const __nv_bfloat16 *Ah, *Al, *Bh, *Bl;
    const float* bias;
    __nv_bfloat16 *outH, *outL;
    float scale = 1.f;
    int m0, n0;
    if (z == 2) {       // V: A = W rows (features), B = X rows
        Ah = g_Wh + 2*WS; Al = g_Wl + 2*WS;
        Bh = g_Xh + 2*XS; Bl = g_Xl + 2*XS;
        bias = bv; outH = g_Vh; outL = g_Vl;
        m0 = blockIdx.x * 128;            // 8 tiles (features)
        n0 = blockIdx.y * 128;            // 32 tiles (tokens)
    } else {
        Ah = g_Xh + (size_t)z*XS; Al = g_Xl + (size_t)z*XS;
        Bh = g_Wh + (size_t)z*WS; Bl = g_Wl + (size_t)z*WS;
        bias = (z == 0) ? bq : bk;
        outH = (z == 0) ? g_Qh : g_Kh;
        outL = (z == 0) ? g_Ql : g_Kl;
        if (z == 0) scale = 0.125f;
        m0 = blockIdx.y * 128;            // 32 tiles (tokens)
        n0 = blockIdx.x * 128;            // 8 tiles (features)
    }

    const int wm0 = (wid & 3) * 32;       // 4 m-warp rows
    const int wn0 = (wid >> 2) * 32;      // 4 n-warp cols
    const int rowin = (l & 7) + ((l >> 3) & 1) * 8;
    const int colb  = ((l >> 4) & 1) * 8;

    const __nv_bfloat16* srcs[4] = { Ah, Al, Bh, Bl };

    float acc[2][4][4];
#pragma unroll
    for (int mt = 0; mt < 2; mt++)
#pragma unroll
        for (int nt = 0; nt < 4; nt++)
#pragma unroll
            for (int i = 0; i < 4; i++) acc[mt][nt][i] = 0.f;

    auto issue = [&](int kt, uint32_t base) {
        const int k0 = kt * 64;
#pragma unroll
        for (int rep = 0; rep < 8; rep++) {
            const int idx = rep * 512 + t;          // 0..4095
            const int mat = idx >> 10;              // 0..3
            const int row = (idx >> 3) & 127;
            const int c   = idx & 7;
            const int grow = (mat < 2 ? m0 : n0) + row;
            const __nv_bfloat16* src = srcs[mat] + (size_t)grow * HH + k0 + c * 8;
            CP_ASYNC16(base + mat * PJ_MAT + row * PJ_ROWB + c * 16, src);
        }
    };

    issue(0, sb);
    CP_COMMIT();

    for (int kt = 0; kt < HH / 64; kt++) {          // 16 iterations
        const uint32_t cur = sb + (kt & 1) * PJ_STG;
        CP_WAIT0();
        __syncthreads();
        if (kt + 1 < HH / 64) {
            issue(kt + 1, sb + ((kt + 1) & 1) * PJ_STG);
            CP_COMMIT();
        }

        const uint32_t AH = cur, AL = cur + PJ_MAT,
                       BH = cur + 2*PJ_MAT, BL = cur + 3*PJ_MAT;
#pragma unroll
        for (int ks = 0; ks < 4; ks++) {
            uint32_t ah[2][4], al[2][4];
#pragma unroll
            for (int mt = 0; mt < 2; mt++) {
                const uint32_t off = (uint32_t)((wm0 + mt*16 + rowin) * PJ_ROWB
                                                + (colb + ks*16) * 2);
                ldm_x4(ah[mt], AH + off);
                ldm_x4(al[mt], AL + off);
            }
            uint32_t bh[4][2], bl[4][2];
#pragma unroll
            for (int np = 0; np < 2; np++) {
                uint32_t r[4];
                const uint32_t off = (uint32_t)((wn0 + np*16 + rowin) * PJ_ROWB
                                                + (colb + ks*16) * 2);
                ldm_x4(r, BH + off);
                bh[2*np][0] = r[0]; bh[2*np][1] = r[2];
                bh[2*np+1][0] = r[1]; bh[2*np+1][1] = r[3];
                ldm_x4(r, BL + off);
                bl[2*np][0] = r[0]; bl[2*np][1] = r[2];
                bl[2*np+1][0] = r[1]; bl[2*np+1][1] = r[3];
            }
#pragma unroll
            for (int mt = 0; mt < 2; mt++)
#pragma unroll
                for (int nt = 0; nt < 4; nt++) {
                    mma_bf16(acc[mt][nt], ah[mt], bh[nt][0], bh[nt][1]);
                    mma_bf16(acc[mt][nt], ah[mt], bl[nt][0], bl[nt][1]);
                    mma_bf16(acc[mt][nt], al[mt], bh[nt][0], bh[nt][1]);
                }
        }
    }

    // ---- epilogue
    const int g    = l >> 2;
    const int tcol = (l & 3) * 2;
#pragma unroll
    for (int mt = 0; mt < 2; mt++) {
#pragma unroll
        for (int nt = 0; nt < 4; nt++) {
            const int gm = m0 + wm0 + mt * 16 + g;
            const int gn = n0 + wn0 + nt * 8 + tcol;
            if (z != 2) {
                const float b0 = __ldg(&bias[gn]), b1 = __ldg(&bias[gn + 1]);
                const int head = gn >> 6, d = gn & 63;
#pragma unroll
                for (int i = 0; i < 2; i++) {
                    const int m = gm + i * 8;
                    const int bb = m >> 11, s = m & 2047;
                    uint32_t hw, lw;
                    split2((acc[mt][nt][2*i]   + b0) * scale,
                           (acc[mt][nt][2*i+1] + b1) * scale, hw, lw);
                    const size_t off = ((size_t)(bb * NHD + head) * SS + s) * HD + d;
                    *(uint32_t*)&outH[off] = hw;
                    *(uint32_t*)&outL[off] = lw;
                }
            } else {
                const int bb = gn >> 11, s = gn & 2047;
#pragma unroll
                for (int i = 0; i < 2; i++) {
                    const int feat = gm + i * 8;
                    const float br = __ldg(&bias[feat]);
                    const int head = feat >> 6, d = feat & 63;
                    uint32_t hw, lw;
                    split2(acc[mt][nt][2*i]   + br,
                           acc[mt][nt][2*i+1] + br, hw, lw);
                    const size_t off = ((size_t)(bb * NHD + head) * HD + d) * SS + s;
                    *(uint32_t*)&outH[off] = hw;
                    *(uint32_t*)&outL[off] = lw;
                }
            }
        }
    }
}

// ===========================================================================
// Flash attention via mma.sync + cp.async 2-stage pipeline.
// CTA: 64 q-rows, 4 warps; target 3 CTAs/SM.
// ===========================================================================
#define AT_ROWB 144
#define AT_MAT  (64*AT_ROWB)             /* 9216 */
#define AT_STG  (4*AT_MAT + 256)         /* 37120: KH, KL, VH, VL, mask */
#define AT_SMEM (2*AT_STG)               /* 74240 */

__global__ __launch_bounds__(128, 3) void attn_mma_kernel(
    const float* __restrict__ mask, float* __restrict__ out)
{
    extern __shared__ __align__(16) uint8_t smem_buf[];
    const uint32_t sb = smem_u32(smem_buf);

    const int t   = threadIdx.x;
    const int wid = t >> 5;
    const int l   = t & 31;
    const int q0  = blockIdx.x * 64;
    const int h   = blockIdx.y;
    const int bz  = blockIdx.z;
    const int bh  = bz * NHD + h;

    const int rowin = (l & 7) + ((l >> 3) & 1) * 8;
    const int colb  = ((l >> 4) & 1) * 8;
    const int g     = l >> 2;
    const int tcol  = (l & 3) * 2;

    const size_t qoff = ((size_t)bh * SS + q0) * HD;
    const size_t koff = (size_t)bh * SS * HD;
    const size_t voff = (size_t)bh * HD * SS;
    const float* mrow_g = mask + (size_t)bz * SS;

    // ---- stage Q (64 x 64, hi/lo) through buffer 0 via cp.async
#pragma unroll
    for (int rep = 0; rep < 8; rep++) {
        const int idx = rep * 128 + t;          // 0..1023
        const int mat = idx >> 9;               // 0: hi, 1: lo
        const int row = (idx >> 3) & 63;
        const int c   = idx & 7;
        const __nv_bfloat16* src = (mat ? g_Ql : g_Qh) + qoff + row * HD + c * 8;
        CP_ASYNC16(sb + mat * AT_MAT + row * AT_ROWB + c * 16, src);
    }
    CP_COMMIT();
    CP_WAIT0();
    __syncthreads();
    uint32_t qh[4][4], ql[4][4];
#pragma unroll
    for (int ks = 0; ks < 4; ks++) {
        const uint32_t off = (uint32_t)((wid*16 + rowin) * AT_ROWB + (colb + ks*16) * 2);
        ldm_x4(qh[ks], sb + off);
        ldm_x4(ql[ks], sb + AT_MAT + off);
    }
    __syncthreads();    // done reading buf0 before KV overwrite

    auto issue_kv = [&](int kt, uint32_t base) {
#pragma unroll
        for (int rep = 0; rep < 16; rep++) {
            const int idx = rep * 128 + t;      // 0..2047
            const int mat = idx >> 9;           // 0..3 : KH, KL, VH, VL
            const int row = (idx >> 3) & 63;
            const int c   = idx & 7;
            const __nv_bfloat16* src;
            if (mat == 0)      src = g_Kh + koff + (size_t)(kt*64 + row) * HD + c*8;
            else if (mat == 1) src = g_Kl + koff + (size_t)(kt*64 + row) * HD + c*8;
            else if (mat == 2) src = g_Vh + voff + (size_t)row * SS + kt*64 + c*8;
            else               src = g_Vl + voff + (size_t)row * SS + kt*64 + c*8;
            CP_ASYNC16(base + mat * AT_MAT + row * AT_ROWB + c * 16, src);
        }
        if (t < 16)
            CP_ASYNC16(base + 4*AT_MAT + t*16, mrow_g + kt*64 + t*4);
    };

    float o[8][4];
#pragma unroll
    for (int dt = 0; dt < 8; dt++)
#pragma unroll
        for (int i = 0; i < 4; i++) o[dt][i] = 0.f;
    float m0r = -1e30f, m1r = -1e30f, l0r = 0.f, l1r = 0.f;

    issue_kv(0, sb);
    CP_COMMIT();

    for (int kt = 0; kt < SS / 64; kt++) {
        const uint32_t cur = sb + (kt & 1) * AT_STG;
        CP_WAIT0();
        __syncthreads();
        if (kt + 1 < SS / 64) {
            issue_kv(kt + 1, sb + ((kt + 1) & 1) * AT_STG);
            CP_COMMIT();
        }

        const uint32_t KH = cur, KL = cur + AT_MAT,
                       VH = cur + 2*AT_MAT, VL = cur + 3*AT_MAT;
        const float* msk = (const float*)(smem_buf + (kt & 1) * AT_STG + 4*AT_MAT);

        // ---- S = Q * K^T
        float s[8][4];
#pragma unroll
        for (int nt = 0; nt < 8; nt++)
#pragma unroll
            for (int i = 0; i < 4; i++) s[nt][i] = 0.f;
#pragma unroll
        for (int ks = 0; ks < 4; ks++) {
#pragma unroll
            for (int np = 0; np < 4; np++) {
                uint32_t kh[4], kl[4];
                const uint32_t off = (uint32_t)((np*16 + rowin) * AT_ROWB
                                                + (colb + ks*16) * 2);
                ldm_x4(kh, KH + off);
                ldm_x4(kl, KL + off);
                const int n0t = 2*np, n1t = 2*np + 1;
                mma_bf16(s[n0t], qh[ks], kh[0], kh[2]);
                mma_bf16(s[n0t], qh[ks], kl[0], kl[2]);
                mma_bf16(s[n0t], ql[ks], kh[0], kh[2]);
                mma_bf16(s[n1t], qh[ks], kh[1], kh[3]);
                mma_bf16(s[n1t], qh[ks], kl[1], kl[3]);
                mma_bf16(s[n1t], ql[ks], kh[1], kh[3]);
            }
        }

        // ---- online softmax
        float rmax0 = -1e30f, rmax1 = -1e30f;
#pragma unroll
        for (int nt = 0; nt < 8; nt++) {
            const float2 mk = *(const float2*)&msk[nt*8 + tcol];
            s[nt][0] += mk.x; s[nt][1] += mk.y;
            s[nt][2] += mk.x; s[nt][3] += mk.y;
            rmax0 = fmaxf(rmax0, fmaxf(s[nt][0], s[nt][1]));
            rmax1 = fmaxf(rmax1, fmaxf(s[nt][2], s[nt][3]));
        }
        rmax0 = fmaxf(rmax0, __shfl_xor_sync(0xFFFFFFFF, rmax0, 1));
        rmax0 = fmaxf(rmax0, __shfl_xor_sync(0xFFFFFFFF, rmax0, 2));
        rmax1 = fmaxf(rmax1, __shfl_xor_sync(0xFFFFFFFF, rmax1, 1));
        rmax1 = fmaxf(rmax1, __shfl_xor_sync(0xFFFFFFFF, rmax1, 2));
        const float mn0 = fmaxf(m0r, rmax0), mn1 = fmaxf(m1r, rmax1);
        const float f0 = __expf(m0r - mn0), f1 = __expf(m1r - mn1);
        m0r = mn0; m1r = mn1;
        float rs0 = 0.f, rs1 = 0.f;
#pragma unroll
        for (int nt = 0; nt < 8; nt++) {
            s[nt][0] = __expf(s[nt][0] - mn0);
            s[nt][1] = __expf(s[nt][1] - mn0);
            s[nt][2] = __expf(s[nt][2] - mn1);
            s[nt][3] = __expf(s[nt][3] - mn1);
            rs0 += s[nt][0] + s[nt][1];
            rs1 += s[nt][2] + s[nt][3];
        }
        rs0 += __shfl_xor_sync(0xFFFFFFFF, rs0, 1);
        rs0 += __shfl_xor_sync(0xFFFFFFFF, rs0, 2);
        rs1 += __shfl_xor_sync(0xFFFFFFFF, rs1, 1);
        rs1 += __shfl_xor_sync(0xFFFFFFFF, rs1, 2);
        l0r = l0r * f0 + rs0;
        l1r = l1r * f1 + rs1;
#pragma unroll
        for (int dt = 0; dt < 8; dt++) {
            o[dt][0] *= f0; o[dt][1] *= f0;
            o[dt][2] *= f1; o[dt][3] *= f1;
        }

        // ---- pack P into bf16 hi/lo A-fragments
        uint32_t ph[4][4], pl[4][4];
#pragma unroll
        for (int ks = 0; ks < 4; ks++) {
            split2(s[2*ks][0],   s[2*ks][1],   ph[ks][0], pl[ks][0]);
            split2(s[2*ks][2],   s[2*ks][3],   ph[ks][1], pl[ks][1]);
            split2(s[2*ks+1][0], s[2*ks+1][1], ph[ks][2], pl[ks][2]);
            split2(s[2*ks+1][2], s[2*ks+1][3], ph[ks][3], pl[ks][3]);
        }

        // ---- O += P * V
#pragma unroll
        for (int ks = 0; ks < 4; ks++) {
#pragma unroll
            for (int dp = 0; dp < 4; dp++) {
                uint32_t vh[4], vl[4];
                const uint32_t off = (uint32_t)((dp*16 + rowin) * AT_ROWB
                                                + (colb + ks*16) * 2);
                ldm_x4(vh, VH + off);
                ldm_x4(vl, VL + off);
                const int d0 = 2*dp, d1 = 2*dp + 1;
                mma_bf16(o[d0], ph[ks], vh[0], vh[2]);
                mma_bf16(o[d0], pl[ks], vh[0], vh[2]);
                mma_bf16(o[d0], ph[ks], vl[0], vl[2]);
                mma_bf16(o[d1], ph[ks], vh[1], vh[3]);
                mma_bf16(o[d1], pl[ks], vh[1], vh[3]);
                mma_bf16(o[d1], ph[ks], vl[1], vl[3]);
            }
        }
    }

    // ---- finalize
    const float inv0 = 1.f / l0r, inv1 = 1.f / l1r;
    const int s0 = q0 + wid * 16 + g;
#pragma unroll
    for (int dt = 0; dt < 8; dt++) {
        const int col = h * HD + dt * 8 + tcol;
        float2 r0; r0.x = o[dt][0] * inv0; r0.y = o[dt][1] * inv0;
        float2 r1; r1.x = o[dt][2] * inv1; r1.y = o[dt][3] * inv1;
        *(float2*)&out[(size_t)(bz * SS + s0)     * HH + col] = r0;
        *(float2*)&out[(size_t)(bz * SS + s0 + 8) * HH + col] = r1;
    }
}

// ---------------------------------------------------------------------------
extern "C" void kernel_launch(void* const* d_in, const int* in_sizes, int n_in,
                              void* d_out, int out_size)
{
    const float* query = (const float*)d_in[0];
    const float* key   = (const float*)d_in[1];
    const float* value = (const float*)d_in[2];
    const float* amask = (const float*)d_in[3];
    const float* bq    = (const float*)d_in[5];
    const float* bk    = (const float*)d_in[7];
    const float* bv    = (const float*)d_in[9];
    float* out = (float*)d_out;

    cudaFuncSetAttribute(proj3_kernel,
                         cudaFuncAttributeMaxDynamicSharedMemorySize, PJ_SMEM);
    cudaFuncSetAttribute(attn_mma_kernel,
                         cudaFuncAttributeMaxDynamicSharedMemorySize, AT_SMEM);

    // ---- fused split (1 launch)
    dim3 sg(1024, 6);
    split6_kernel<<<sg, 256>>>(query, key, value,
                               (const float*)d_in[4], (const float*)d_in[6],
                               (const float*)d_in[8]);

    // ---- fused projections (1 launch): grid (8, 32, 3)
    dim3 pg(HH / 128, MM / 128, 3);
    proj3_kernel<<<pg, 512, PJ_SMEM>>>(bq, bk, bv);

    // ---- attention
    dim3 ag(SS / 64, NHD, BB);     // (32, 16, 2) = 1024 CTAs
    attn_mma_kernel<<<ag, 128, AT_SMEM>>>(amask, out);
}

// round 11
// speedup vs baseline: 4.5966x; 1.4382x over previous
#include <cuda_runtime.h>
#include <cuda_bf16.h>
#include <cuda_fp16.h>
#include <stdint.h>
#include <stddef.h>

#define BB 2
#define SS 2048
#define HH 1024
#define NHD 16
#define HD 64
#define MM (BB*SS)   /* 4096 */

#define LOG2E 1.4426950408889634f

// ---- split inputs (hi/lo bf16) for projections -----------------------------
__device__ __align__(16) __nv_bfloat16 g_Xh[3u*MM*HH];
__device__ __align__(16) __nv_bfloat16 g_Xl[3u*MM*HH];
__device__ __align__(16) __nv_bfloat16 g_Wh[3u*HH*HH];
__device__ __align__(16) __nv_bfloat16 g_Wl[3u*HH*HH];

// ---- projected tensors, single fp16 ----------------------------------------
// Q, K: [b, h, s, d] row-major (Q pre-scaled by 0.125*log2e).
// V: [b, h, d, s] (transposed).
__device__ __align__(16) __half g_Qf[MM*HH];
__device__ __align__(16) __half g_Kf[MM*HH];
__device__ __align__(16) __half g_Vf[MM*HH];
__device__ __align__(16) float  g_Msk[BB*SS];   // mask * log2e

// ---------------------------------------------------------------------------
// helpers
// ---------------------------------------------------------------------------
__device__ __forceinline__ uint32_t smem_u32(const void* p) {
    uint32_t a;
    asm("{ .reg .u64 t; cvta.to.shared.u64 t, %1; cvt.u32.u64 %0, t; }"
        : "=r"(a) : "l"(p));
    return a;
}

__device__ __forceinline__ void split2(float x, float y, uint32_t& h, uint32_t& l) {
    __nv_bfloat162 hh = __floats2bfloat162_rn(x, y);
    float2 hf = __bfloat1622float2(hh);
    __nv_bfloat162 ll = __floats2bfloat162_rn(x - hf.x, y - hf.y);
    h = *reinterpret_cast<uint32_t*>(&hh);
    l = *reinterpret_cast<uint32_t*>(&ll);
}

__device__ __forceinline__ uint32_t packh2(float x, float y) {
    __half2 h = __floats2half2_rn(x, y);
    return *reinterpret_cast<uint32_t*>(&h);
}

__device__ __forceinline__ float ex2f(float x) {
    float y;
    asm("ex2.approx.f32 %0, %1;" : "=f"(y) : "f"(x));
    return y;
}

__device__ __forceinline__ void ldm_x4(uint32_t r[4], uint32_t addr) {
    asm volatile("ldmatrix.sync.aligned.m8n8.x4.shared.b16 {%0,%1,%2,%3}, [%4];"
                 : "=r"(r[0]), "=r"(r[1]), "=r"(r[2]), "=r"(r[3]) : "r"(addr));
}

__device__ __forceinline__ void mma_bf16(float c[4], const uint32_t a[4],
                                         uint32_t b0, uint32_t b1) {
    asm volatile("mma.sync.aligned.m16n8k16.row.col.f32.bf16.bf16.f32 "
                 "{%0,%1,%2,%3}, {%4,%5,%6,%7}, {%8,%9}, {%0,%1,%2,%3};"
                 : "+f"(c[0]), "+f"(c[1]), "+f"(c[2]), "+f"(c[3])
                 : "r"(a[0]), "r"(a[1]), "r"(a[2]), "r"(a[3]), "r"(b0), "r"(b1));
}

__device__ __forceinline__ void mma_f16(float c[4], const uint32_t a[4],
                                        uint32_t b0, uint32_t b1) {
    asm volatile("mma.sync.aligned.m16n8k16.row.col.f32.f16.f16.f32 "
                 "{%0,%1,%2,%3}, {%4,%5,%6,%7}, {%8,%9}, {%0,%1,%2,%3};"
                 : "+f"(c[0]), "+f"(c[1]), "+f"(c[2]), "+f"(c[3])
                 : "r"(a[0]), "r"(a[1]), "r"(a[2]), "r"(a[3]), "r"(b0), "r"(b1));
}

#define CP_ASYNC16(dst, src) \
    asm volatile("cp.async.cg.shared.global [%0], [%1], 16;" \
                 :: "r"(dst), "l"(src) : "memory")
#define CP_COMMIT()  asm volatile("cp.async.commit_group;" ::: "memory")
#define CP_WAIT0()   asm volatile("cp.async.wait_group 0;" ::: "memory")

// ===========================================================================
// fused split kernel: 6 fp32->bf16hi/lo segments + mask*log2e (seg 6)
// ===========================================================================
__global__ __launch_bounds__(256) void split6_kernel(
    const float* __restrict__ q, const float* __restrict__ k,
    const float* __restrict__ v, const float* __restrict__ wq,
    const float* __restrict__ wk, const float* __restrict__ wv,
    const float* __restrict__ msk)
{
    const int seg = blockIdx.y;
    const int stride = gridDim.x * blockDim.x;
    const size_t XS = (size_t)MM * HH, WS = (size_t)HH * HH;

    if (seg == 6) {     // mask scale
        const int n4 = BB * SS / 4;
        for (int i = blockIdx.x * blockDim.x + threadIdx.x; i < n4; i += stride) {
            float4 f = ((const float4*)msk)[i];
            f.x *= LOG2E; f.y *= LOG2E; f.z *= LOG2E; f.w *= LOG2E;
            ((float4*)g_Msk)[i] = f;
        }
        return;
    }

    const float* in;
    __nv_bfloat16 *hi, *lo;
    int n4;
    switch (seg) {
        case 0: in = q;  hi = g_Xh;        lo = g_Xl;        n4 = MM*HH/4; break;
        case 1: in = k;  hi = g_Xh + XS;   lo = g_Xl + XS;   n4 = MM*HH/4; break;
        case 2: in = v;  hi = g_Xh + 2*XS; lo = g_Xl + 2*XS; n4 = MM*HH/4; break;
        case 3: in = wq; hi = g_Wh;        lo = g_Wl;        n4 = HH*HH/4; break;
        case 4: in = wk; hi = g_Wh + WS;   lo = g_Wl + WS;   n4 = HH*HH/4; break;
        default:in = wv; hi = g_Wh + 2*WS; lo = g_Wl + 2*WS; n4 = HH*HH/4; break;
    }
    for (int i = blockIdx.x * blockDim.x + threadIdx.x; i < n4; i += stride) {
        float4 f = ((const float4*)in)[i];
        uint32_t h0, h1, l0, l1;
        split2(f.x, f.y, h0, l0);
        split2(f.z, f.w, h1, l1);
        ((uint2*)hi)[i] = make_uint2(h0, h1);
        ((uint2*)lo)[i] = make_uint2(l0, l1);
    }
}

// ===========================================================================
// Fused projection GEMM (Q, K, V via blockIdx.z), mma.sync bf16x3,
// cp.async 2-stage. CTA 128x128, BK=64, 512 threads, warp tile 32x32.
// Outputs single fp16. Q scale = 0.125*log2e.
// ===========================================================================
#define PJ_ROWB 144
#define PJ_MAT  (128*PJ_ROWB)            /* 18432 */
#define PJ_STG  (4*PJ_MAT)               /* 73728 */
#define PJ_SMEM (2*PJ_STG)               /* 147456 */

__global__ __launch_bounds__(512, 1) void proj3_kernel(
    const float* __restrict__ bq, const float* __restrict__ bk,
    const float* __restrict__ bv)
{
    extern __shared__ __align__(16) uint8_t psm[];
    const uint32_t sb = smem_u32(psm);

    const int z   = blockIdx.z;
    const int t   = threadIdx.x;
    const int wid = t >> 5;
    const int l   = t & 31;

    const size_t XS = (size_t)MM * HH, WS = (size_t)HH * HH;
    const __nv_bfloat16 *Ah, *Al, *Bh, *Bl;
    const float* bias;
    __half* outF;
    float scale = 1.f;
    int m0, n0;
    if (z == 2) {
        Ah = g_Wh + 2*WS; Al = g_Wl + 2*WS;
        Bh = g_Xh + 2*XS; Bl = g_Xl + 2*XS;
        bias = bv; outF = g_Vf;
        m0 = blockIdx.x * 128;
        n0 = blockIdx.y * 128;
    } else {
        Ah = g_Xh + (size_t)z*XS; Al = g_Xl + (size_t)z*XS;
        Bh = g_Wh + (size_t)z*WS; Bl = g_Wl + (size_t)z*WS;
        bias = (z == 0) ? bq : bk;
        outF = (z == 0) ? g_Qf : g_Kf;
        if (z == 0) scale = 0.125f * LOG2E;
        m0 = blockIdx.y * 128;
        n0 = blockIdx.x * 128;
    }

    const int wm0 = (wid & 3) * 32;
    const int wn0 = (wid >> 2) * 32;
    const int rowin = (l & 7) + ((l >> 3) & 1) * 8;
    const int colb  = ((l >> 4) & 1) * 8;

    const __nv_bfloat16* srcs[4] = { Ah, Al, Bh, Bl };

    float acc[2][4][4];
#pragma unroll
    for (int mt = 0; mt < 2; mt++)
#pragma unroll
        for (int nt = 0; nt < 4; nt++)
#pragma unroll
            for (int i = 0; i < 4; i++) acc[mt][nt][i] = 0.f;

    auto issue = [&](int kt, uint32_t base) {
        const int k0 = kt * 64;
#pragma unroll
        for (int rep = 0; rep < 8; rep++) {
            const int idx = rep * 512 + t;
            const int mat = idx >> 10;
            const int row = (idx >> 3) & 127;
            const int c   = idx & 7;
            const int grow = (mat < 2 ? m0 : n0) + row;
            const __nv_bfloat16* src = srcs[mat] + (size_t)grow * HH + k0 + c * 8;
            CP_ASYNC16(base + mat * PJ_MAT + row * PJ_ROWB + c * 16, src);
        }
    };

    issue(0, sb);
    CP_COMMIT();

    for (int kt = 0; kt < HH / 64; kt++) {
        const uint32_t cur = sb + (kt & 1) * PJ_STG;
        CP_WAIT0();
        __syncthreads();
        if (kt + 1 < HH / 64) {
            issue(kt + 1, sb + ((kt + 1) & 1) * PJ_STG);
            CP_COMMIT();
        }

        const uint32_t AH = cur, AL = cur + PJ_MAT,
                       BH = cur + 2*PJ_MAT, BL = cur + 3*PJ_MAT;
#pragma unroll
        for (int ks = 0; ks < 4; ks++) {
            uint32_t ah[2][4], al[2][4];
#pragma unroll
            for (int mt = 0; mt < 2; mt++) {
                const uint32_t off = (uint32_t)((wm0 + mt*16 + rowin) * PJ_ROWB
                                                + (colb + ks*16) * 2);
                ldm_x4(ah[mt], AH + off);
                ldm_x4(al[mt], AL + off);
            }
            uint32_t bh[4][2], bl[4][2];
#pragma unroll
            for (int np = 0; np < 2; np++) {
                uint32_t r[4];
                const uint32_t off = (uint32_t)((wn0 + np*16 + rowin) * PJ_ROWB
                                                + (colb + ks*16) * 2);
                ldm_x4(r, BH + off);
                bh[2*np][0] = r[0]; bh[2*np][1] = r[2];
                bh[2*np+1][0] = r[1]; bh[2*np+1][1] = r[3];
                ldm_x4(r, BL + off);
                bl[2*np][0] = r[0]; bl[2*np][1] = r[2];
                bl[2*np+1][0] = r[1]; bl[2*np+1][1] = r[3];
            }
#pragma unroll
            for (int mt = 0; mt < 2; mt++)
#pragma unroll
                for (int nt = 0; nt < 4; nt++) {
                    mma_bf16(acc[mt][nt], ah[mt], bh[nt][0], bh[nt][1]);
                    mma_bf16(acc[mt][nt], ah[mt], bl[nt][0], bl[nt][1]);
                    mma_bf16(acc[mt][nt], al[mt], bh[nt][0], bh[nt][1]);
                }
        }
    }

    // ---- epilogue: +bias, *scale, fp16 store
    const int g    = l >> 2;
    const int tcol = (l & 3) * 2;
#pragma unroll
    for (int mt = 0; mt < 2; mt++) {
#pragma unroll
        for (int nt = 0; nt < 4; nt++) {
            const int gm = m0 + wm0 + mt * 16 + g;
            const int gn = n0 + wn0 + nt * 8 + tcol;
            if (z != 2) {
                const float b0 = __ldg(&bias[gn]), b1 = __ldg(&bias[gn + 1]);
                const int head = gn >> 6, d = gn & 63;
#pragma unroll
                for (int i = 0; i < 2; i++) {
                    const int m = gm + i * 8;
                    const int bb = m >> 11, s = m & 2047;
                    const uint32_t w = packh2((acc[mt][nt][2*i]   + b0) * scale,
                                              (acc[mt][nt][2*i+1] + b1) * scale);
                    *(uint32_t*)&outF[((size_t)(bb * NHD + head) * SS + s) * HD + d] = w;
                }
            } else {
                const int bb = gn >> 11, s = gn & 2047;
#pragma unroll
                for (int i = 0; i < 2; i++) {
                    const int feat = gm + i * 8;
                    const float br = __ldg(&bias[feat]);
                    const int head = feat >> 6, d = feat & 63;
                    const uint32_t w = packh2(acc[mt][nt][2*i]   + br,
                                              acc[mt][nt][2*i+1] + br);
                    *(uint32_t*)&outF[((size_t)(bb * NHD + head) * HD + d) * SS + s] = w;
                }
            }
        }
    }
}

// ===========================================================================
// Flash attention, single-fp16 mma, base-2 softmax, cp.async 2-stage.
// CTA: 64 q-rows, 4 warps, 4 CTAs/SM target.
// ===========================================================================
#define AT_ROWB 144
#define AT_MAT  (64*AT_ROWB)             /* 9216 */
#define AT_STG  (2*AT_MAT + 256)         /* 18688: KF, VF, mask */
#define AT_SMEM (2*AT_STG)               /* 37376 */

__global__ __launch_bounds__(128, 4) void attn_mma_kernel(float* __restrict__ out)
{
    extern __shared__ __align__(16) uint8_t smem_buf[];
    const uint32_t sb = smem_u32(smem_buf);

    const int t   = threadIdx.x;
    const int wid = t >> 5;
    const int l   = t & 31;
    const int q0  = blockIdx.x * 64;
    const int h   = blockIdx.y;
    const int bz  = blockIdx.z;
    const int bh  = bz * NHD + h;

    const int rowin = (l & 7) + ((l >> 3) & 1) * 8;
    const int colb  = ((l >> 4) & 1) * 8;
    const int g     = l >> 2;
    const int tcol  = (l & 3) * 2;

    const size_t qoff = ((size_t)bh * SS + q0) * HD;
    const size_t koff = (size_t)bh * SS * HD;
    const size_t voff = (size_t)bh * HD * SS;
    const float* mrow_g = g_Msk + (size_t)bz * SS;

    // ---- stage Q (64 x 64 fp16) through buffer 0
#pragma unroll
    for (int rep = 0; rep < 4; rep++) {
        const int idx = rep * 128 + t;          // 0..511
        const int row = idx >> 3;
        const int c   = idx & 7;
        CP_ASYNC16(sb + row * AT_ROWB + c * 16, g_Qf + qoff + row * HD + c * 8);
    }
    CP_COMMIT();
    CP_WAIT0();
    __syncthreads();
    uint32_t qf[4][4];
#pragma unroll
    for (int ks = 0; ks < 4; ks++) {
        const uint32_t off = (uint32_t)((wid*16 + rowin) * AT_ROWB + (colb + ks*16) * 2);
        ldm_x4(qf[ks], sb + off);
    }
    __syncthreads();

    auto issue_kv = [&](int kt, uint32_t base) {
#pragma unroll
        for (int rep = 0; rep < 8; rep++) {
            const int idx = rep * 128 + t;      // 0..1023
            const int mat = idx >> 9;           // 0: KF, 1: VF
            const int row = (idx >> 3) & 63;
            const int c   = idx & 7;
            const __half* src = (mat == 0)
                ? g_Kf + koff + (size_t)(kt*64 + row) * HD + c*8
                : g_Vf + voff + (size_t)row * SS + kt*64 + c*8;
            CP_ASYNC16(base + mat * AT_MAT + row * AT_ROWB + c * 16, src);
        }
        if (t < 16)
            CP_ASYNC16(base + 2*AT_MAT + t*16, mrow_g + kt*64 + t*4);
    };

    float o[8][4];
#pragma unroll
    for (int dt = 0; dt < 8; dt++)
#pragma unroll
        for (int i = 0; i < 4; i++) o[dt][i] = 0.f;
    float m0r = -1e30f, m1r = -1e30f, l0r = 0.f, l1r = 0.f;

    issue_kv(0, sb);
    CP_COMMIT();

    for (int kt = 0; kt < SS / 64; kt++) {
        const uint32_t cur = sb + (kt & 1) * AT_STG;
        CP_WAIT0();
        __syncthreads();
        if (kt + 1 < SS / 64) {
            issue_kv(kt + 1, sb + ((kt + 1) & 1) * AT_STG);
            CP_COMMIT();
        }

        const uint32_t KF = cur, VF = cur + AT_MAT;
        const float* msk = (const float*)(smem_buf + (kt & 1) * AT_STG + 2*AT_MAT);

        // ---- S = Q * K^T (base-2 logits: scale folded into Q, mask pre-scaled)
        float s[8][4];
#pragma unroll
        for (int nt = 0; nt < 8; nt++)
#pragma unroll
            for (int i = 0; i < 4; i++) s[nt][i] = 0.f;
#pragma unroll
        for (int ks = 0; ks < 4; ks++) {
#pragma unroll
            for (int np = 0; np < 4; np++) {
                uint32_t kf[4];
                const uint32_t off = (uint32_t)((np*16 + rowin) * AT_ROWB
                                                + (colb + ks*16) * 2);
                ldm_x4(kf, KF + off);
                mma_f16(s[2*np],   qf[ks], kf[0], kf[2]);
                mma_f16(s[2*np+1], qf[ks], kf[1], kf[3]);
            }
        }

        // ---- online softmax (base 2)
        float rmax0 = -1e30f, rmax1 = -1e30f;
#pragma unroll
        for (int nt = 0; nt < 8; nt++) {
            const float2 mk = *(const float2*)&msk[nt*8 + tcol];
            s[nt][0] += mk.x; s[nt][1] += mk.y;
            s[nt][2] += mk.x; s[nt][3] += mk.y;
            rmax0 = fmaxf(rmax0, fmaxf(s[nt][0], s[nt][1]));
            rmax1 = fmaxf(rmax1, fmaxf(s[nt][2], s[nt][3]));
        }
        rmax0 = fmaxf(rmax0, __shfl_xor_sync(0xFFFFFFFF, rmax0, 1));
        rmax0 = fmaxf(rmax0, __shfl_xor_sync(0xFFFFFFFF, rmax0, 2));
        rmax1 = fmaxf(rmax1, __shfl_xor_sync(0xFFFFFFFF, rmax1, 1));
        rmax1 = fmaxf(rmax1, __shfl_xor_sync(0xFFFFFFFF, rmax1, 2));
        const float mn0 = fmaxf(m0r, rmax0), mn1 = fmaxf(m1r, rmax1);
        const float f0 = ex2f(m0r - mn0), f1 = ex2f(m1r - mn1);
        m0r = mn0; m1r = mn1;
        float rs0 = 0.f, rs1 = 0.f;
#pragma unroll
        for (int nt = 0; nt < 8; nt++) {
            s[nt][0] = ex2f(s[nt][0] - mn0);
            s[nt][1] = ex2f(s[nt][1] - mn0);
            s[nt][2] = ex2f(s[nt][2] - mn1);
            s[nt][3] = ex2f(s[nt][3] - mn1);
            rs0 += s[nt][0] + s[nt][1];
            rs1 += s[nt][2] + s[nt][3];
        }
        rs0 += __shfl_xor_sync(0xFFFFFFFF, rs0, 1);
        rs0 += __shfl_xor_sync(0xFFFFFFFF, rs0, 2);
        rs1 += __shfl_xor_sync(0xFFFFFFFF, rs1, 1);
        rs1 += __shfl_xor_sync(0xFFFFFFFF, rs1, 2);
        l0r = l0r * f0 + rs0;
        l1r = l1r * f1 + rs1;
#pragma unroll
        for (int dt = 0; dt < 8; dt++) {
            o[dt][0] *= f0; o[dt][1] *= f0;
            o[dt][2] *= f1; o[dt][3] *= f1;
        }

        // ---- pack P to fp16 A-fragments
        uint32_t pf[4][4];
#pragma unroll
        for (int ks = 0; ks < 4; ks++) {
            pf[ks][0] = packh2(s[2*ks][0],   s[2*ks][1]);
            pf[ks][1] = packh2(s[2*ks][2],   s[2*ks][3]);
            pf[ks][2] = packh2(s[2*ks+1][0], s[2*ks+1][1]);
            pf[ks][3] = packh2(s[2*ks+1][2], s[2*ks+1][3]);
        }

        // ---- O += P * V
#pragma unroll
        for (int ks = 0; ks < 4; ks++) {
#pragma unroll
            for (int dp = 0; dp < 4; dp++) {
                uint32_t vf[4];
                const uint32_t off = (uint32_t)((dp*16 + rowin) * AT_ROWB
                                                + (colb + ks*16) * 2);
                ldm_x4(vf, VF + off);
                mma_f16(o[2*dp],   pf[ks], vf[0], vf[2]);
                mma_f16(o[2*dp+1], pf[ks], vf[1], vf[3]);
            }
        }
    }

    // ---- finalize
    const float inv0 = 1.f / l0r, inv1 = 1.f / l1r;
    const int s0 = q0 + wid * 16 + g;
#pragma unroll
    for (int dt = 0; dt < 8; dt++) {
        const int col = h * HD + dt * 8 + tcol;
        float2 r0; r0.x = o[dt][0] * inv0; r0.y = o[dt][1] * inv0;
        float2 r1; r1.x = o[dt][2] * inv1; r1.y = o[dt][3] * inv1;
        *(float2*)&out[(size_t)(bz * SS + s0)     * HH + col] = r0;
        *(float2*)&out[(size_t)(bz * SS + s0 + 8) * HH + col] = r1;
    }
}

// ---------------------------------------------------------------------------
extern "C" void kernel_launch(void* const* d_in, const int* in_sizes, int n_in,
                              void* d_out, int out_size)
{
    const float* query = (const float*)d_in[0];
    const float* key   = (const float*)d_in[1];
    const float* value = (const float*)d_in[2];
    const float* amask = (const float*)d_in[3];
    const float* bq    = (const float*)d_in[5];
    const float* bk    = (const float*)d_in[7];
    const float* bv    = (const float*)d_in[9];
    float* out = (float*)d_out;

    cudaFuncSetAttribute(proj3_kernel,
                         cudaFuncAttributeMaxDynamicSharedMemorySize, PJ_SMEM);
    cudaFuncSetAttribute(attn_mma_kernel,
                         cudaFuncAttributeMaxDynamicSharedMemorySize, AT_SMEM);

    // ---- fused split + mask scale (1 launch)
    dim3 sg(1024, 7);
    split6_kernel<<<sg, 256>>>(query, key, value,
                               (const float*)d_in[4], (const float*)d_in[6],
                               (const float*)d_in[8], amask);

    // ---- fused projections (1 launch)
    dim3 pg(HH / 128, MM / 128, 3);
    proj3_kernel<<<pg, 512, PJ_SMEM>>>(bq, bk, bv);

    // ---- attention
    dim3 ag(SS / 64, NHD, BB);     // (32, 16, 2) = 1024 CTAs
    attn_mma_kernel<<<ag, 128, AT_SMEM>>>(out);
}

// round 12
// speedup vs baseline: 7.6312x; 1.6602x over previous
#include <cuda_runtime.h>
#include <cuda_fp16.h>
#include <stdint.h>
#include <stddef.h>

#define BB 2
#define SS 2048
#define HH 1024
#define NHD 16
#define HD 64
#define MM (BB*SS)   /* 4096 */

#define LOG2E 1.4426950408889634f

// ---- fp16 inputs for projections -------------------------------------------
__device__ __align__(16) __half g_Xf[3u*MM*HH];
__device__ __align__(16) __half g_Wf[3u*HH*HH];

// ---- projected tensors, fp16 ------------------------------------------------
// Q, K: [b, h, s, d] row-major (Q pre-scaled by 0.125*log2e).
// V: [b, h, d, s] (transposed).
__device__ __align__(16) __half g_Qf[MM*HH];
__device__ __align__(16) __half g_Kf[MM*HH];
__device__ __align__(16) __half g_Vf[MM*HH];
__device__ __align__(16) float  g_Msk[BB*SS];   // mask * log2e

// ---------------------------------------------------------------------------
// helpers
// ---------------------------------------------------------------------------
__device__ __forceinline__ uint32_t smem_u32(const void* p) {
    uint32_t a;
    asm("{ .reg .u64 t; cvta.to.shared.u64 t, %1; cvt.u32.u64 %0, t; }"
        : "=r"(a) : "l"(p));
    return a;
}

__device__ __forceinline__ uint32_t packh2(float x, float y) {
    __half2 h = __floats2half2_rn(x, y);
    return *reinterpret_cast<uint32_t*>(&h);
}

__device__ __forceinline__ float ex2f(float x) {
    float y;
    asm("ex2.approx.f32 %0, %1;" : "=f"(y) : "f"(x));
    return y;
}

__device__ __forceinline__ void ldm_x4(uint32_t r[4], uint32_t addr) {
    asm volatile("ldmatrix.sync.aligned.m8n8.x4.shared.b16 {%0,%1,%2,%3}, [%4];"
                 : "=r"(r[0]), "=r"(r[1]), "=r"(r[2]), "=r"(r[3]) : "r"(addr));
}

__device__ __forceinline__ void mma_f16(float c[4], const uint32_t a[4],
                                        uint32_t b0, uint32_t b1) {
    asm volatile("mma.sync.aligned.m16n8k16.row.col.f32.f16.f16.f32 "
                 "{%0,%1,%2,%3}, {%4,%5,%6,%7}, {%8,%9}, {%0,%1,%2,%3};"
                 : "+f"(c[0]), "+f"(c[1]), "+f"(c[2]), "+f"(c[3])
                 : "r"(a[0]), "r"(a[1]), "r"(a[2]), "r"(a[3]), "r"(b0), "r"(b1));
}

#define CP_ASYNC16(dst, src) \
    asm volatile("cp.async.cg.shared.global [%0], [%1], 16;" \
                 :: "r"(dst), "l"(src) : "memory")
#define CP_COMMIT()  asm volatile("cp.async.commit_group;" ::: "memory")
#define CP_WAIT0()   asm volatile("cp.async.wait_group 0;" ::: "memory")

// ===========================================================================
// fused convert kernel: 6 fp32->fp16 segments + mask*log2e (seg 6)
// ===========================================================================
__global__ __launch_bounds__(256) void split6_kernel(
    const float* __restrict__ q, const float* __restrict__ k,
    const float* __restrict__ v, const float* __restrict__ wq,
    const float* __restrict__ wk, const float* __restrict__ wv,
    const float* __restrict__ msk)
{
    const int seg = blockIdx.y;
    const int stride = gridDim.x * blockDim.x;
    const size_t XS = (size_t)MM * HH, WS = (size_t)HH * HH;

    if (seg == 6) {     // mask scale
        const int n4 = BB * SS / 4;
        for (int i = blockIdx.x * blockDim.x + threadIdx.x; i < n4; i += stride) {
            float4 f = ((const float4*)msk)[i];
            f.x *= LOG2E; f.y *= LOG2E; f.z *= LOG2E; f.w *= LOG2E;
            ((float4*)g_Msk)[i] = f;
        }
        return;
    }

    const float* in;
    __half* dst;
    int n4;
    switch (seg) {
        case 0: in = q;  dst = g_Xf;        n4 = MM*HH/4; break;
        case 1: in = k;  dst = g_Xf + XS;   n4 = MM*HH/4; break;
        case 2: in = v;  dst = g_Xf + 2*XS; n4 = MM*HH/4; break;
        case 3: in = wq; dst = g_Wf;        n4 = HH*HH/4; break;
        case 4: in = wk; dst = g_Wf + WS;   n4 = HH*HH/4; break;
        default:in = wv; dst = g_Wf + 2*WS; n4 = HH*HH/4; break;
    }
    for (int i = blockIdx.x * blockDim.x + threadIdx.x; i < n4; i += stride) {
        float4 f = ((const float4*)in)[i];
        ((uint2*)dst)[i] = make_uint2(packh2(f.x, f.y), packh2(f.z, f.w));
    }
}

// ===========================================================================
// Fused projection GEMM (Q, K, V via blockIdx.z), single fp16 mma.sync,
// cp.async 2-stage. CTA 128x128, BK=64, 256 threads, warp tile 64x32,
// 2 CTAs/SM.
//   z=0,1 (Q,K): C[m,n] = X[m,:]·W[n,:]; out=(C+bias[n])*scale -> [b,h,s,d]
//   z=2   (V):   A=W, B=X -> C=(X@W^T)^T; out stored [b,h,d,s], bias[m-row]
// ===========================================================================
#define PJ_ROWB 144                      /* 128B data + 16B pad */
#define PJ_MAT  (128*PJ_ROWB)            /* 18432 */
#define PJ_STG  (2*PJ_MAT)               /* 36864: AF, BF */
#define PJ_SMEM (2*PJ_STG)               /* 73728 */

__global__ __launch_bounds__(256, 2) void proj3_kernel(
    const float* __restrict__ bq, const float* __restrict__ bk,
    const float* __restrict__ bv)
{
    extern __shared__ __align__(16) uint8_t psm[];
    const uint32_t sb = smem_u32(psm);

    const int z   = blockIdx.z;
    const int t   = threadIdx.x;
    const int wid = t >> 5;
    const int l   = t & 31;

    const size_t XS = (size_t)MM * HH, WS = (size_t)HH * HH;
    const __half *Af, *Bf;
    const float* bias;
    __half* outF;
    float scale = 1.f;
    int m0, n0;
    if (z == 2) {
        Af = g_Wf + 2*WS;
        Bf = g_Xf + 2*XS;
        bias = bv; outF = g_Vf;
        m0 = blockIdx.x * 128;
        n0 = blockIdx.y * 128;
    } else {
        Af = g_Xf + (size_t)z*XS;
        Bf = g_Wf + (size_t)z*WS;
        bias = (z == 0) ? bq : bk;
        outF = (z == 0) ? g_Qf : g_Kf;
        if (z == 0) scale = 0.125f * LOG2E;
        m0 = blockIdx.y * 128;
        n0 = blockIdx.x * 128;
    }

    const int wm0 = (wid & 1) * 64;       // 2 m-warp rows
    const int wn0 = (wid >> 1) * 32;      // 4 n-warp cols
    const int rowin = (l & 7) + ((l >> 3) & 1) * 8;
    const int colb  = ((l >> 4) & 1) * 8;

    float acc[4][4][4];
#pragma unroll
    for (int mt = 0; mt < 4; mt++)
#pragma unroll
        for (int nt = 0; nt < 4; nt++)
#pragma unroll
            for (int i = 0; i < 4; i++) acc[mt][nt][i] = 0.f;

    auto issue = [&](int kt, uint32_t base) {
        const int k0 = kt * 64;
#pragma unroll
        for (int rep = 0; rep < 8; rep++) {
            const int idx = rep * 256 + t;          // 0..2047
            const int mat = idx >> 10;              // 0: A, 1: B
            const int row = (idx >> 3) & 127;
            const int c   = idx & 7;
            const int grow = (mat == 0 ? m0 : n0) + row;
            const __half* src = (mat == 0 ? Af : Bf) + (size_t)grow * HH + k0 + c * 8;
            CP_ASYNC16(base + mat * PJ_MAT + row * PJ_ROWB + c * 16, src);
        }
    };

    issue(0, sb);
    CP_COMMIT();

    for (int kt = 0; kt < HH / 64; kt++) {          // 16 iterations
        const uint32_t cur = sb + (kt & 1) * PJ_STG;
        CP_WAIT0();
        __syncthreads();
        if (kt + 1 < HH / 64) {
            issue(kt + 1, sb + ((kt + 1) & 1) * PJ_STG);
            CP_COMMIT();
        }

        const uint32_t AF = cur, BF = cur + PJ_MAT;
#pragma unroll
        for (int ks = 0; ks < 4; ks++) {
            uint32_t af[4][4];
#pragma unroll
            for (int mt = 0; mt < 4; mt++) {
                const uint32_t off = (uint32_t)((wm0 + mt*16 + rowin) * PJ_ROWB
                                                + (colb + ks*16) * 2);
                ldm_x4(af[mt], AF + off);
            }
            uint32_t bf[4][2];
#pragma unroll
            for (int np = 0; np < 2; np++) {
                uint32_t r[4];
                const uint32_t off = (uint32_t)((wn0 + np*16 + rowin) * PJ_ROWB
                                                + (colb + ks*16) * 2);
                ldm_x4(r, BF + off);
                bf[2*np][0] = r[0]; bf[2*np][1] = r[2];
                bf[2*np+1][0] = r[1]; bf[2*np+1][1] = r[3];
            }
#pragma unroll
            for (int mt = 0; mt < 4; mt++)
#pragma unroll
                for (int nt = 0; nt < 4; nt++)
                    mma_f16(acc[mt][nt], af[mt], bf[nt][0], bf[nt][1]);
        }
    }

    // ---- epilogue: +bias, *scale, fp16 store
    const int g    = l >> 2;
    const int tcol = (l & 3) * 2;
#pragma unroll
    for (int mt = 0; mt < 4; mt++) {
#pragma unroll
        for (int nt = 0; nt < 4; nt++) {
            const int gm = m0 + wm0 + mt * 16 + g;
            const int gn = n0 + wn0 + nt * 8 + tcol;
            if (z != 2) {
                const float b0 = __ldg(&bias[gn]), b1 = __ldg(&bias[gn + 1]);
                const int head = gn >> 6, d = gn & 63;
#pragma unroll
                for (int i = 0; i < 2; i++) {
                    const int m = gm + i * 8;
                    const int bb = m >> 11, s = m & 2047;
                    const uint32_t w = packh2((acc[mt][nt][2*i]   + b0) * scale,
                                              (acc[mt][nt][2*i+1] + b1) * scale);
                    *(uint32_t*)&outF[((size_t)(bb * NHD + head) * SS + s) * HD + d] = w;
                }
            } else {
                const int bb = gn >> 11, s = gn & 2047;
#pragma unroll
                for (int i = 0; i < 2; i++) {
                    const int feat = gm + i * 8;
                    const float br = __ldg(&bias[feat]);
                    const int head = feat >> 6, d = feat & 63;
                    const uint32_t w = packh2(acc[mt][nt][2*i]   + br,
                                              acc[mt][nt][2*i+1] + br);
                    *(uint32_t*)&outF[((size_t)(bb * NHD + head) * HD + d) * SS + s] = w;
                }
            }
        }
    }
}

// ===========================================================================
// Flash attention, single-fp16 mma, base-2 softmax, cp.async 2-stage.
// CTA: 64 q-rows, 4 warps, 4 CTAs/SM.
// ===========================================================================
#define AT_ROWB 144
#define AT_MAT  (64*AT_ROWB)             /* 9216 */
#define AT_STG  (2*AT_MAT + 256)         /* 18688: KF, VF, mask */
#define AT_SMEM (2*AT_STG)               /* 37376 */

__global__ __launch_bounds__(128, 4) void attn_mma_kernel(float* __restrict__ out)
{
    extern __shared__ __align__(16) uint8_t smem_buf[];
    const uint32_t sb = smem_u32(smem_buf);

    const int t   = threadIdx.x;
    const int wid = t >> 5;
    const int l   = t & 31;
    const int q0  = blockIdx.x * 64;
    const int h   = blockIdx.y;
    const int bz  = blockIdx.z;
    const int bh  = bz * NHD + h;

    const int rowin = (l & 7) + ((l >> 3) & 1) * 8;
    const int colb  = ((l >> 4) & 1) * 8;
    const int g     = l >> 2;
    const int tcol  = (l & 3) * 2;

    const size_t qoff = ((size_t)bh * SS + q0) * HD;
    const size_t koff = (size_t)bh * SS * HD;
    const size_t voff = (size_t)bh * HD * SS;
    const float* mrow_g = g_Msk + (size_t)bz * SS;

    // ---- stage Q (64 x 64 fp16) through buffer 0
#pragma unroll
    for (int rep = 0; rep < 4; rep++) {
        const int idx = rep * 128 + t;          // 0..511
        const int row = idx >> 3;
        const int c   = idx & 7;
        CP_ASYNC16(sb + row * AT_ROWB + c * 16, g_Qf + qoff + row * HD + c * 8);
    }
    CP_COMMIT();
    CP_WAIT0();
    __syncthreads();
    uint32_t qf[4][4];
#pragma unroll
    for (int ks = 0; ks < 4; ks++) {
        const uint32_t off = (uint32_t)((wid*16 + rowin) * AT_ROWB + (colb + ks*16) * 2);
        ldm_x4(qf[ks], sb + off);
    }
    __syncthreads();

    auto issue_kv = [&](int kt, uint32_t base) {
#pragma unroll
        for (int rep = 0; rep < 8; rep++) {
            const int idx = rep * 128 + t;      // 0..1023
            const int mat = idx >> 9;           // 0: KF, 1: VF
            const int row = (idx >> 3) & 63;
            const int c   = idx & 7;
            const __half* src = (mat == 0)
                ? g_Kf + koff + (size_t)(kt*64 + row) * HD + c*8
                : g_Vf + voff + (size_t)row * SS + kt*64 + c*8;
            CP_ASYNC16(base + mat * AT_MAT + row * AT_ROWB + c * 16, src);
        }
        if (t < 16)
            CP_ASYNC16(base + 2*AT_MAT + t*16, mrow_g + kt*64 + t*4);
    };

    float o[8][4];
#pragma unroll
    for (int dt = 0; dt < 8; dt++)
#pragma unroll
        for (int i = 0; i < 4; i++) o[dt][i] = 0.f;
    float m0r = -1e30f, m1r = -1e30f, l0r = 0.f, l1r = 0.f;

    issue_kv(0, sb);
    CP_COMMIT();

    for (int kt = 0; kt < SS / 64; kt++) {
        const uint32_t cur = sb + (kt & 1) * AT_STG;
        CP_WAIT0();
        __syncthreads();
        if (kt + 1 < SS / 64) {
            issue_kv(kt + 1, sb + ((kt + 1) & 1) * AT_STG);
            CP_COMMIT();
        }

        const uint32_t KF = cur, VF = cur + AT_MAT;
        const float* msk = (const float*)(smem_buf + (kt & 1) * AT_STG + 2*AT_MAT);

        // ---- S = Q * K^T (base-2 logits)
        float s[8][4];
#pragma unroll
        for (int nt = 0; nt < 8; nt++)
#pragma unroll
            for (int i = 0; i < 4; i++) s[nt][i] = 0.f;
#pragma unroll
        for (int ks = 0; ks < 4; ks++) {
#pragma unroll
            for (int np = 0; np < 4; np++) {
                uint32_t kf[4];
                const uint32_t off = (uint32_t)((np*16 + rowin) * AT_ROWB
                                                + (colb + ks*16) * 2);
                ldm_x4(kf, KF + off);
                mma_f16(s[2*np],   qf[ks], kf[0], kf[2]);
                mma_f16(s[2*np+1], qf[ks], kf[1], kf[3]);
            }
        }

        // ---- online softmax (base 2)
        float rmax0 = -1e30f, rmax1 = -1e30f;
#pragma unroll
        for (int nt = 0; nt < 8; nt++) {
            const float2 mk = *(const float2*)&msk[nt*8 + tcol];
            s[nt][0] += mk.x; s[nt][1] += mk.y;
            s[nt][2] += mk.x; s[nt][3] += mk.y;
            rmax0 = fmaxf(rmax0, fmaxf(s[nt][0], s[nt][1]));
            rmax1 = fmaxf(rmax1, fmaxf(s[nt][2], s[nt][3]));
        }
        rmax0 = fmaxf(rmax0, __shfl_xor_sync(0xFFFFFFFF, rmax0, 1));
        rmax0 = fmaxf(rmax0, __shfl_xor_sync(0xFFFFFFFF, rmax0, 2));
        rmax1 = fmaxf(rmax1, __shfl_xor_sync(0xFFFFFFFF, rmax1, 1));
        rmax1 = fmaxf(rmax1, __shfl_xor_sync(0xFFFFFFFF, rmax1, 2));
        const float mn0 = fmaxf(m0r, rmax0), mn1 = fmaxf(m1r, rmax1);
        const float f0 = ex2f(m0r - mn0), f1 = ex2f(m1r - mn1);
        m0r = mn0; m1r = mn1;
        float rs0 = 0.f, rs1 = 0.f;
#pragma unroll
        for (int nt = 0; nt < 8; nt++) {
            s[nt][0] = ex2f(s[nt][0] - mn0);
            s[nt][1] = ex2f(s[nt][1] - mn0);
            s[nt][2] = ex2f(s[nt][2] - mn1);
            s[nt][3] = ex2f(s[nt][3] - mn1);
            rs0 += s[nt][0] + s[nt][1];
            rs1 += s[nt][2] + s[nt][3];
        }
        rs0 += __shfl_xor_sync(0xFFFFFFFF, rs0, 1);
        rs0 += __shfl_xor_sync(0xFFFFFFFF, rs0, 2);
        rs1 += __shfl_xor_sync(0xFFFFFFFF, rs1, 1);
        rs1 += __shfl_xor_sync(0xFFFFFFFF, rs1, 2);
        l0r = l0r * f0 + rs0;
        l1r = l1r * f1 + rs1;
#pragma unroll
        for (int dt = 0; dt < 8; dt++) {
            o[dt][0] *= f0; o[dt][1] *= f0;
            o[dt][2] *= f1; o[dt][3] *= f1;
        }

        // ---- pack P to fp16 A-fragments
        uint32_t pf[4][4];
#pragma unroll
        for (int ks = 0; ks < 4; ks++) {
            pf[ks][0] = packh2(s[2*ks][0],   s[2*ks][1]);
            pf[ks][1] = packh2(s[2*ks][2],   s[2*ks][3]);
            pf[ks][2] = packh2(s[2*ks+1][0], s[2*ks+1][1]);
            pf[ks][3] = packh2(s[2*ks+1][2], s[2*ks+1][3]);
        }

        // ---- O += P * V
#pragma unroll
        for (int ks = 0; ks < 4; ks++) {
#pragma unroll
            for (int dp = 0; dp < 4; dp++) {
                uint32_t vf[4];
                const uint32_t off = (uint32_t)((dp*16 + rowin) * AT_ROWB
                                                + (colb + ks*16) * 2);
                ldm_x4(vf, VF + off);
                mma_f16(o[2*dp],   pf[ks], vf[0], vf[2]);
                mma_f16(o[2*dp+1], pf[ks], vf[1], vf[3]);
            }
        }
    }

    // ---- finalize
    const float inv0 = 1.f / l0r, inv1 = 1.f / l1r;
    const int s0 = q0 + wid * 16 + g;
#pragma unroll
    for (int dt = 0; dt < 8; dt++) {
        const int col = h * HD + dt * 8 + tcol;
        float2 r0; r0.x = o[dt][0] * inv0; r0.y = o[dt][1] * inv0;
        float2 r1; r1.x = o[dt][2] * inv1; r1.y = o[dt][3] * inv1;
        *(float2*)&out[(size_t)(bz * SS + s0)     * HH + col] = r0;
        *(float2*)&out[(size_t)(bz * SS + s0 + 8) * HH + col] = r1;
    }
}

// ---------------------------------------------------------------------------
extern "C" void kernel_launch(void* const* d_in, const int* in_sizes, int n_in,
                              void* d_out, int out_size)
{
    const float* query = (const float*)d_in[0];
    const float* key   = (const float*)d_in[1];
    const float* value = (const float*)d_in[2];
    const float* amask = (const float*)d_in[3];
    const float* bq    = (const float*)d_in[5];
    const float* bk    = (const float*)d_in[7];
    const float* bv    = (const float*)d_in[9];
    float* out = (float*)d_out;

    cudaFuncSetAttribute(proj3_kernel,
                         cudaFuncAttributeMaxDynamicSharedMemorySize, PJ_SMEM);
    cudaFuncSetAttribute(attn_mma_kernel,
                         cudaFuncAttributeMaxDynamicSharedMemorySize, AT_SMEM);

    // ---- fused convert + mask scale (1 launch)
    dim3 sg(1024, 7);
    split6_kernel<<<sg, 256>>>(query, key, value,
                               (const float*)d_in[4], (const float*)d_in[6],
                               (const float*)d_in[8], amask);

    // ---- fused projections (1 launch)
    dim3 pg(HH / 128, MM / 128, 3);
    proj3_kernel<<<pg, 256, PJ_SMEM>>>(bq, bk, bv);

    // ---- attention
    dim3 ag(SS / 64, NHD, BB);     // (32, 16, 2) = 1024 CTAs
    attn_mma_kernel<<<ag, 128, AT_SMEM>>>(out);
}